// round 1
// baseline (speedup 1.0000x reference)
#include <cuda_runtime.h>
#include <cuda_bf16.h>
#include <math.h>

// Problem constants
#define T_TOK   4096
#define DIM     2048
#define NH      16
#define NKV     4
#define HD      128
#define QB      64
#define KBLK    64
#define KSTR    129   // smem row stride for 128-wide tiles (odd -> conflict-friendly)
#define SSTR    65    // smem row stride for 64-wide score tile

// -------- scratch (device globals; no allocation allowed) --------
__device__ float g_Q[T_TOK * NH * HD];      // 32 MB
__device__ float g_K[T_TOK * NKV * HD];     // 8 MB
__device__ float g_V[T_TOK * NKV * HD];     // 8 MB
__device__ float g_A[T_TOK * NH * HD];      // 32 MB

// ----------------------------------------------------------------
// SGEMM: C[M,N] = A[M,K] @ B[K,N], all row-major, M%128==0, N%128==0, K%16==0
// 128x128 block tile, BK=16, 256 threads, 8x8 per thread.
// Column micro-mapping c = tx + 16*j  -> conflict-free Bs reads, coalesced C writes.
// ----------------------------------------------------------------
__global__ void __launch_bounds__(256) sgemm128(const float* __restrict__ A,
                                                const float* __restrict__ B,
                                                float* __restrict__ C,
                                                int M, int N, int K)
{
    __shared__ float As[16][128];
    __shared__ float Bs[16][128];
    const int tid = threadIdx.x;
    const int tx = tid & 15, ty = tid >> 4;
    const int bm = blockIdx.y * 128, bn = blockIdx.x * 128;

    float acc[8][8];
#pragma unroll
    for (int i = 0; i < 8; i++)
#pragma unroll
        for (int j = 0; j < 8; j++) acc[i][j] = 0.f;

    for (int k0 = 0; k0 < K; k0 += 16) {
#pragma unroll
        for (int i = 0; i < 2; i++) {
            int lin = tid + i * 256;
            // A tile: 128 rows x 16 cols
            int r  = lin >> 2;
            int c4 = (lin & 3) * 4;
            float4 a = *(const float4*)(A + (size_t)(bm + r) * K + k0 + c4);
            As[c4 + 0][r] = a.x; As[c4 + 1][r] = a.y;
            As[c4 + 2][r] = a.z; As[c4 + 3][r] = a.w;
            // B tile: 16 rows x 128 cols
            int rb = lin >> 5;
            int cb = (lin & 31) * 4;
            *(float4*)&Bs[rb][cb] = *(const float4*)(B + (size_t)(k0 + rb) * N + bn + cb);
        }
        __syncthreads();
#pragma unroll
        for (int kk = 0; kk < 16; kk++) {
            float ra[8], rb[8];
#pragma unroll
            for (int i = 0; i < 8; i++) ra[i] = As[kk][ty * 8 + i];
#pragma unroll
            for (int j = 0; j < 8; j++) rb[j] = Bs[kk][tx + 16 * j];
#pragma unroll
            for (int i = 0; i < 8; i++)
#pragma unroll
                for (int j = 0; j < 8; j++)
                    acc[i][j] = fmaf(ra[i], rb[j], acc[i][j]);
        }
        __syncthreads();
    }
#pragma unroll
    for (int i = 0; i < 8; i++) {
        size_t row = (size_t)(bm + ty * 8 + i);
#pragma unroll
        for (int j = 0; j < 8; j++)
            C[row * N + bn + tx + 16 * j] = acc[i][j];
    }
}

// ----------------------------------------------------------------
// RoPE on Q (T x 16 x 128) and K (T x 4 x 128); pairs (2j, 2j+1).
// ----------------------------------------------------------------
__global__ void rope_kernel(float* __restrict__ Q, float* __restrict__ K,
                            const float* __restrict__ fcos,
                            const float* __restrict__ fsin)
{
    int idx = blockIdx.x * blockDim.x + threadIdx.x; // T*(NH+NKV)*64 total
    int pair = idx & 63;
    int rest = idx >> 6;
    int h = rest % (NH + NKV);
    int t = rest / (NH + NKV);
    float c = fcos[t * 64 + pair];
    float s = fsin[t * 64 + pair];
    float* p;
    if (h < NH) p = Q + ((size_t)t * NH + h) * HD + pair * 2;
    else        p = K + ((size_t)t * NKV + (h - NH)) * HD + pair * 2;
    float x0 = p[0], x1 = p[1];
    p[0] = x0 * c - x1 * s;
    p[1] = x0 * s + x1 * c;
}

// ----------------------------------------------------------------
// Flash attention, 64-query tile per block, one head per blockIdx.y.
// Online softmax, O accumulators in registers (4 rows x 8 cols / thread).
// Masks: causal + same sequence id. Key blocks entirely in earlier
// sequences are skipped.
// ----------------------------------------------------------------
__global__ void __launch_bounds__(256) flash_kernel(const float* __restrict__ Q,
                                                    const float* __restrict__ K,
                                                    const float* __restrict__ V,
                                                    const int* __restrict__ sid,
                                                    float* __restrict__ Aout)
{
    extern __shared__ float sm[];
    float* Qs   = sm;                    // 64 x KSTR
    float* Ks   = Qs + QB * KSTR;        // 64 x KSTR
    float* Vs   = Ks + KBLK * KSTR;      // 64 x KSTR
    float* Ss   = Vs + KBLK * KSTR;      // 64 x SSTR
    float* mrow = Ss + QB * SSTR;        // 64
    float* lrow = mrow + QB;             // 64
    float* arow = lrow + QB;             // 64
    int*   sq   = (int*)(arow + QB);     // 64
    int*   sk   = sq + QB;               // 64

    const int qb = blockIdx.x;
    const int h  = blockIdx.y;
    const int kh = h >> 2;               // N_REP = 4
    const int tid = threadIdx.x;
    const int tx = tid & 15, ty = tid >> 4;
    const int ty4 = ty * 4;

    // Load Q tile (64 x 128)
#pragma unroll
    for (int i = 0; i < 8; i++) {
        int lin = tid + i * 256;
        int r = lin >> 5;
        int c4 = (lin & 31) * 4;
        float4 v = *(const float4*)(Q + ((size_t)(qb * QB + r) * NH + h) * HD + c4);
        Qs[r * KSTR + c4 + 0] = v.x; Qs[r * KSTR + c4 + 1] = v.y;
        Qs[r * KSTR + c4 + 2] = v.z; Qs[r * KSTR + c4 + 3] = v.w;
    }
    if (tid < QB) {
        sq[tid]   = sid[qb * QB + tid];
        mrow[tid] = -3.0e38f;
        lrow[tid] = 0.f;
    }
    __syncthreads();
    const int sq_first = sq[0];

    float acc[4][8];
#pragma unroll
    for (int i = 0; i < 4; i++)
#pragma unroll
        for (int j = 0; j < 8; j++) acc[i][j] = 0.f;

    const float scale = 0.08838834764831845f; // 1/sqrt(128)

    for (int kb = 0; kb <= qb; kb++) {
        // Skip key blocks entirely in earlier sequences (seq_ids non-decreasing)
        if (sid[kb * KBLK + KBLK - 1] < sq_first) continue;

        __syncthreads(); // protect Ks/Vs/Ss from previous iteration readers

        // Load K,V tiles (64 x 128 each)
#pragma unroll
        for (int i = 0; i < 8; i++) {
            int lin = tid + i * 256;
            int r = lin >> 5;
            int c4 = (lin & 31) * 4;
            size_t goff = ((size_t)(kb * KBLK + r) * NKV + kh) * HD + c4;
            float4 kv = *(const float4*)(K + goff);
            Ks[r * KSTR + c4 + 0] = kv.x; Ks[r * KSTR + c4 + 1] = kv.y;
            Ks[r * KSTR + c4 + 2] = kv.z; Ks[r * KSTR + c4 + 3] = kv.w;
            float4 vv = *(const float4*)(V + goff);
            Vs[r * KSTR + c4 + 0] = vv.x; Vs[r * KSTR + c4 + 1] = vv.y;
            Vs[r * KSTR + c4 + 2] = vv.z; Vs[r * KSTR + c4 + 3] = vv.w;
        }
        if (tid < KBLK) sk[tid] = sid[kb * KBLK + tid];
        __syncthreads();

        // S = Q @ K^T  (rows ty4..ty4+3, cols tx + 16*j)
        float s[4][4];
#pragma unroll
        for (int i = 0; i < 4; i++)
#pragma unroll
            for (int j = 0; j < 4; j++) s[i][j] = 0.f;

#pragma unroll 4
        for (int d = 0; d < HD; d++) {
            float q0 = Qs[(ty4 + 0) * KSTR + d];
            float q1 = Qs[(ty4 + 1) * KSTR + d];
            float q2 = Qs[(ty4 + 2) * KSTR + d];
            float q3 = Qs[(ty4 + 3) * KSTR + d];
            float k0 = Ks[(tx +  0) * KSTR + d];
            float k1 = Ks[(tx + 16) * KSTR + d];
            float k2 = Ks[(tx + 32) * KSTR + d];
            float k3 = Ks[(tx + 48) * KSTR + d];
            s[0][0] = fmaf(q0, k0, s[0][0]); s[0][1] = fmaf(q0, k1, s[0][1]);
            s[0][2] = fmaf(q0, k2, s[0][2]); s[0][3] = fmaf(q0, k3, s[0][3]);
            s[1][0] = fmaf(q1, k0, s[1][0]); s[1][1] = fmaf(q1, k1, s[1][1]);
            s[1][2] = fmaf(q1, k2, s[1][2]); s[1][3] = fmaf(q1, k3, s[1][3]);
            s[2][0] = fmaf(q2, k0, s[2][0]); s[2][1] = fmaf(q2, k1, s[2][1]);
            s[2][2] = fmaf(q2, k2, s[2][2]); s[2][3] = fmaf(q2, k3, s[2][3]);
            s[3][0] = fmaf(q3, k0, s[3][0]); s[3][1] = fmaf(q3, k1, s[3][1]);
            s[3][2] = fmaf(q3, k2, s[3][2]); s[3][3] = fmaf(q3, k3, s[3][3]);
        }

        // mask + scale + store to Ss
        const int qi0 = qb * QB, ki0 = kb * KBLK;
#pragma unroll
        for (int i = 0; i < 4; i++) {
            int r = ty4 + i;
            int qi = qi0 + r;
            int sqr = sq[r];
#pragma unroll
            for (int j = 0; j < 4; j++) {
                int c = tx + 16 * j;
                int ki = ki0 + c;
                float val = s[i][j] * scale;
                if (ki > qi || sk[c] != sqr) val = -1.0e30f;
                Ss[r * SSTR + c] = val;
            }
        }
        __syncthreads();

        // online softmax update: 4 threads per row
        {
            int r = tid >> 2, l4 = tid & 3;
            float mx = -3.0e38f;
            for (int c = l4; c < KBLK; c += 4) mx = fmaxf(mx, Ss[r * SSTR + c]);
            mx = fmaxf(mx, __shfl_xor_sync(0xffffffffu, mx, 1));
            mx = fmaxf(mx, __shfl_xor_sync(0xffffffffu, mx, 2));
            float mold = mrow[r];
            float mnew = fmaxf(mold, mx);
            float sum = 0.f;
            for (int c = l4; c < KBLK; c += 4) {
                float p = __expf(Ss[r * SSTR + c] - mnew);
                Ss[r * SSTR + c] = p;
                sum += p;
            }
            sum += __shfl_xor_sync(0xffffffffu, sum, 1);
            sum += __shfl_xor_sync(0xffffffffu, sum, 2);
            if (l4 == 0) {
                float al = __expf(mold - mnew);
                arow[r] = al;
                lrow[r] = lrow[r] * al + sum;
                mrow[r] = mnew;
            }
        }
        __syncthreads();

        // O = O*alpha + P @ V   (rows ty4.., cols tx + 16*j)
        {
            float al0 = arow[ty4 + 0], al1 = arow[ty4 + 1];
            float al2 = arow[ty4 + 2], al3 = arow[ty4 + 3];
#pragma unroll
            for (int j = 0; j < 8; j++) {
                acc[0][j] *= al0; acc[1][j] *= al1;
                acc[2][j] *= al2; acc[3][j] *= al3;
            }
#pragma unroll 2
            for (int k = 0; k < KBLK; k++) {
                float p0 = Ss[(ty4 + 0) * SSTR + k];
                float p1 = Ss[(ty4 + 1) * SSTR + k];
                float p2 = Ss[(ty4 + 2) * SSTR + k];
                float p3 = Ss[(ty4 + 3) * SSTR + k];
#pragma unroll
                for (int j = 0; j < 8; j++) {
                    float v = Vs[k * KSTR + tx + 16 * j];
                    acc[0][j] = fmaf(p0, v, acc[0][j]);
                    acc[1][j] = fmaf(p1, v, acc[1][j]);
                    acc[2][j] = fmaf(p2, v, acc[2][j]);
                    acc[3][j] = fmaf(p3, v, acc[3][j]);
                }
            }
        }
    }

    // epilogue: divide by l, write out (layout T x (NH*HD))
#pragma unroll
    for (int i = 0; i < 4; i++) {
        int r = ty4 + i;
        float inv = 1.0f / lrow[r];
        size_t base = ((size_t)(qb * QB + r) * NH + h) * HD;
#pragma unroll
        for (int j = 0; j < 8; j++)
            Aout[base + tx + 16 * j] = acc[i][j] * inv;
    }
}

// ----------------------------------------------------------------
extern "C" void kernel_launch(void* const* d_in, const int* in_sizes, int n_in,
                              void* d_out, int out_size)
{
    const float* x   = (const float*)d_in[0];
    const float* wq  = (const float*)d_in[1];
    const float* wk  = (const float*)d_in[2];
    const float* wv  = (const float*)d_in[3];
    const float* wo  = (const float*)d_in[4];
    const float* fc  = (const float*)d_in[5];
    const float* fs  = (const float*)d_in[6];
    const int*   sid = (const int*)d_in[7];
    float* out = (float*)d_out;

    float *Qp, *Kp, *Vp, *Ap;
    cudaGetSymbolAddress((void**)&Qp, g_Q);
    cudaGetSymbolAddress((void**)&Kp, g_K);
    cudaGetSymbolAddress((void**)&Vp, g_V);
    cudaGetSymbolAddress((void**)&Ap, g_A);

    // QKV projections
    sgemm128<<<dim3(DIM / 128, T_TOK / 128), 256>>>(x, wq, Qp, T_TOK, DIM, DIM);
    sgemm128<<<dim3((NKV * HD) / 128, T_TOK / 128), 256>>>(x, wk, Kp, T_TOK, NKV * HD, DIM);
    sgemm128<<<dim3((NKV * HD) / 128, T_TOK / 128), 256>>>(x, wv, Vp, T_TOK, NKV * HD, DIM);

    // RoPE on Q and K
    rope_kernel<<<(T_TOK * (NH + NKV) * 64) / 256, 256>>>(Qp, Kp, fc, fs);

    // Flash attention
    size_t smem = (size_t)(3 * QB * KSTR + QB * SSTR + 3 * QB) * sizeof(float)
                + (size_t)(2 * QB) * sizeof(int);
    cudaFuncSetAttribute(flash_kernel, cudaFuncAttributeMaxDynamicSharedMemorySize, (int)smem);
    flash_kernel<<<dim3(T_TOK / QB, NH), 256, smem>>>(Qp, Kp, Vp, sid, Ap);

    // Output projection
    sgemm128<<<dim3(DIM / 128, T_TOK / 128), 256>>>(Ap, wo, out, T_TOK, DIM, DIM);
}

// round 7
// speedup vs baseline: 1.7743x; 1.7743x over previous
#include <cuda_runtime.h>
#include <cuda_fp16.h>
#include <cstdint>
#include <math.h>

// ---------------- problem constants ----------------
#define T_TOK   4096
#define DIM     2048
#define NH      16
#define NKV     4
#define HD      128
#define QB      64
#define KBLK    64
#define KSTR    129
#define SSTR    65

// ---------------- HMMA GEMM constants ----------------
#define BM 128
#define BN 128
#define BK 32
#define PADK 40                       // fp16 per smem row (80B -> 20-bank stride, conflict-free)
#define MAT_BYTES (128 * PADK * 2)    // 10240 B per matrix tile
#define STAGE_B   (4 * MAT_BYTES)     // Ah, Al, Bh, Bl
#define NSTAGE 3
#define GEMM_SMEM (NSTAGE * STAGE_B)  // 122880 B

// single dynamic-smem symbol for the whole TU
extern __shared__ __align__(16) char dyn_smem[];

// -------- scratch (device globals; no allocation allowed) --------
__device__ float g_Q[T_TOK * NH * HD];
__device__ float g_K[T_TOK * NKV * HD];
__device__ float g_V[T_TOK * NKV * HD];
__device__ float g_A[T_TOK * NH * HD];
__device__ __half g_xh[T_TOK * DIM],  g_xl[T_TOK * DIM];     // x split
__device__ __half g_ah[T_TOK * DIM],  g_al[T_TOK * DIM];     // attn-out split
__device__ __half g_wqkvh[3072 * DIM], g_wqkvl[3072 * DIM];  // [N=3072][K] transposed
__device__ __half g_woh[DIM * DIM],   g_wol[DIM * DIM];      // [N=2048][K] transposed

// ---------------- helpers ----------------
__device__ __forceinline__ void cp16(void* dst, const void* src) {
    uint32_t d;
    asm("{ .reg .u64 t; cvta.to.shared.u64 t, %1; cvt.u32.u64 %0, t; }" : "=r"(d) : "l"(dst));
    asm volatile("cp.async.cg.shared.global [%0], [%1], 16;" :: "r"(d), "l"(src));
}
__device__ __forceinline__ void mma16816(float* c, const uint32_t* a, const uint32_t* b) {
    asm volatile(
        "mma.sync.aligned.m16n8k16.row.col.f32.f16.f16.f32 "
        "{%0,%1,%2,%3}, {%4,%5,%6,%7}, {%8,%9}, {%0,%1,%2,%3};"
        : "+f"(c[0]), "+f"(c[1]), "+f"(c[2]), "+f"(c[3])
        : "r"(a[0]), "r"(a[1]), "r"(a[2]), "r"(a[3]), "r"(b[0]), "r"(b[1]));
}

// ---------------- pack: fp32 -> (hi, lo) fp16, same layout ----------------
__global__ void __launch_bounds__(256) pack_split(const float* __restrict__ in,
                                                  __half* __restrict__ oh,
                                                  __half* __restrict__ ol, int n4) {
    int i = blockIdx.x * blockDim.x + threadIdx.x;
    if (i >= n4) return;
    float4 v = ((const float4*)in)[i];
    __half h0 = __float2half_rn(v.x), h1 = __float2half_rn(v.y);
    __half h2 = __float2half_rn(v.z), h3 = __float2half_rn(v.w);
    __half l0 = __float2half_rn(v.x - __half2float(h0));
    __half l1 = __float2half_rn(v.y - __half2float(h1));
    __half l2 = __float2half_rn(v.z - __half2float(h2));
    __half l3 = __float2half_rn(v.w - __half2float(h3));
    ((__half2*)oh)[i * 2 + 0] = __halves2half2(h0, h1);
    ((__half2*)oh)[i * 2 + 1] = __halves2half2(h2, h3);
    ((__half2*)ol)[i * 2 + 0] = __halves2half2(l0, l1);
    ((__half2*)ol)[i * 2 + 1] = __halves2half2(l2, l3);
}

// ---------------- pack: w[K][Nsrc] fp32 -> transposed [nbase+n][K] (hi, lo) fp16 ----------------
__global__ void __launch_bounds__(256) pack_wT(const float* __restrict__ w,
                                               __half* __restrict__ oh,
                                               __half* __restrict__ ol,
                                               int Nsrc, int nbase) {
    __shared__ float t[32][33];
    int k0 = blockIdx.x * 32, n0 = blockIdx.y * 32;
    int tid = threadIdx.x;
    int cc = tid & 31, rr = tid >> 5;
#pragma unroll
    for (int i = 0; i < 4; i++) {
        int row = rr + i * 8;
        t[row][cc] = w[(size_t)(k0 + row) * Nsrc + n0 + cc];
    }
    __syncthreads();
#pragma unroll
    for (int i = 0; i < 4; i++) {
        int n = rr + i * 8;
        float v = t[cc][n];
        __half h = __float2half_rn(v);
        __half l = __float2half_rn(v - __half2float(h));
        size_t o = (size_t)(nbase + n0 + n) * DIM + k0 + cc;
        oh[o] = h;
        ol[o] = l;
    }
}

// ---------------- HMMA GEMM: C[4096, N] = A @ B^T(stored [N][K]), fp16x3 ----------------
__global__ void __launch_bounds__(128, 1) gemm_hmma(const __half* __restrict__ Ah,
                                                    const __half* __restrict__ Al,
                                                    const __half* __restrict__ Bh,
                                                    const __half* __restrict__ Bl,
                                                    float* __restrict__ Cq,
                                                    float* __restrict__ Ck,
                                                    float* __restrict__ Cv) {
    char* sm = dyn_smem;
    const int tid = threadIdx.x;
    const int wid = tid >> 5, lane = tid & 31;
    const int wm = (wid & 1) * 64, wn = (wid >> 1) * 64;
    const int lg = lane >> 2, lt = lane & 3;

    const size_t arow0 = (size_t)blockIdx.y * BM;
    const size_t brow0 = (size_t)blockIdx.x * BN;

    float acc[4][8][4];
#pragma unroll
    for (int mf = 0; mf < 4; mf++)
#pragma unroll
        for (int nf = 0; nf < 8; nf++)
#pragma unroll
            for (int q = 0; q < 4; q++) acc[mf][nf][q] = 0.f;

    const int NKT = DIM / BK;   // 64

#define G_ISSUE(KT, ST) do {                                                     \
    char* _sb = sm + (ST) * STAGE_B;                                             \
    int _k0 = (KT) * BK;                                                         \
    _Pragma("unroll")                                                            \
    for (int _i = 0; _i < 16; _i++) {                                            \
        int _idx = tid + _i * 128;          /* 0..2047 */                        \
        int _mat = _idx >> 9;                                                    \
        int _rem = _idx & 511;                                                   \
        int _row = _rem >> 2;                                                    \
        int _ch  = _rem & 3;                                                     \
        const __half* _src;                                                      \
        if (_mat == 0)      _src = Ah + (arow0 + _row) * DIM + _k0 + _ch * 8;    \
        else if (_mat == 1) _src = Al + (arow0 + _row) * DIM + _k0 + _ch * 8;    \
        else if (_mat == 2) _src = Bh + (brow0 + _row) * DIM + _k0 + _ch * 8;    \
        else                _src = Bl + (brow0 + _row) * DIM + _k0 + _ch * 8;    \
        cp16(_sb + _mat * MAT_BYTES + _row * 80 + _ch * 16, _src);               \
    }                                                                            \
    asm volatile("cp.async.commit_group;" ::: "memory");                         \
} while (0)

    G_ISSUE(0, 0);
    G_ISSUE(1, 1);

    for (int kt = 0; kt < NKT; kt++) {
        int st = kt % NSTAGE;
        if (kt + 1 < NKT) asm volatile("cp.async.wait_group 1;" ::: "memory");
        else              asm volatile("cp.async.wait_group 0;" ::: "memory");
        __syncthreads();
        if (kt + 2 < NKT) G_ISSUE(kt + 2, (kt + 2) % NSTAGE);

        const uint32_t* sAh = (const uint32_t*)(sm + st * STAGE_B);
        const uint32_t* sAl = sAh + MAT_BYTES / 4;
        const uint32_t* sBh = sAl + MAT_BYTES / 4;
        const uint32_t* sBl = sBh + MAT_BYTES / 4;

#pragma unroll
        for (int ks = 0; ks < 2; ks++) {
            uint32_t ah[4][4], al[4][4];
            const int cb = lt + ks * 8;
#pragma unroll
            for (int mf = 0; mf < 4; mf++) {
                int r0 = (wm + mf * 16 + lg) * (PADK / 2);
                int r1 = r0 + 8 * (PADK / 2);
                ah[mf][0] = sAh[r0 + cb];     ah[mf][1] = sAh[r1 + cb];
                ah[mf][2] = sAh[r0 + cb + 4]; ah[mf][3] = sAh[r1 + cb + 4];
                al[mf][0] = sAl[r0 + cb];     al[mf][1] = sAl[r1 + cb];
                al[mf][2] = sAl[r0 + cb + 4]; al[mf][3] = sAl[r1 + cb + 4];
            }
#pragma unroll
            for (int nf = 0; nf < 8; nf++) {
                int nr = (wn + nf * 8 + lg) * (PADK / 2);
                uint32_t bh[2], bl[2];
                bh[0] = sBh[nr + cb]; bh[1] = sBh[nr + cb + 4];
                bl[0] = sBl[nr + cb]; bl[1] = sBl[nr + cb + 4];
#pragma unroll
                for (int mf = 0; mf < 4; mf++) {
                    mma16816(acc[mf][nf], ah[mf], bh);
                    mma16816(acc[mf][nf], ah[mf], bl);
                    mma16816(acc[mf][nf], al[mf], bh);
                }
            }
        }
    }

    // ---- epilogue ----
    float* Cb;
    int stride, colofs;
    int nblock = blockIdx.x * BN;
    if (Ck == nullptr || nblock < 2048) { Cb = Cq; stride = 2048; colofs = nblock; }
    else if (nblock < 2560)             { Cb = Ck; stride = 512;  colofs = nblock - 2048; }
    else                                { Cb = Cv; stride = 512;  colofs = nblock - 2560; }

#pragma unroll
    for (int mf = 0; mf < 4; mf++) {
        size_t row0 = arow0 + wm + mf * 16 + lg;
#pragma unroll
        for (int nf = 0; nf < 8; nf++) {
            int col = colofs + wn + nf * 8 + lt * 2;
            *(float2*)(Cb + row0 * stride + col) =
                make_float2(acc[mf][nf][0], acc[mf][nf][1]);
            *(float2*)(Cb + (row0 + 8) * stride + col) =
                make_float2(acc[mf][nf][2], acc[mf][nf][3]);
        }
    }
}

// ---------------- RoPE ----------------
__global__ void rope_kernel(float* __restrict__ Q, float* __restrict__ K,
                            const float* __restrict__ fcos,
                            const float* __restrict__ fsin)
{
    int idx = blockIdx.x * blockDim.x + threadIdx.x;
    int pair = idx & 63;
    int rest = idx >> 6;
    int h = rest % (NH + NKV);
    int t = rest / (NH + NKV);
    float c = fcos[t * 64 + pair];
    float s = fsin[t * 64 + pair];
    float* p;
    if (h < NH) p = Q + ((size_t)t * NH + h) * HD + pair * 2;
    else        p = K + ((size_t)t * NKV + (h - NH)) * HD + pair * 2;
    float x0 = p[0], x1 = p[1];
    p[0] = x0 * c - x1 * s;
    p[1] = x0 * s + x1 * c;
}

// ---------------- Flash attention (fp32) ----------------
__global__ void __launch_bounds__(256) flash_kernel(const float* __restrict__ Q,
                                                    const float* __restrict__ K,
                                                    const float* __restrict__ V,
                                                    const int* __restrict__ sid,
                                                    float* __restrict__ Aout)
{
    float* smf = (float*)dyn_smem;
    float* Qs   = smf;
    float* Ks   = Qs + QB * KSTR;
    float* Vs   = Ks + KBLK * KSTR;
    float* Ss   = Vs + KBLK * KSTR;
    float* mrow = Ss + QB * SSTR;
    float* lrow = mrow + QB;
    float* arow = lrow + QB;
    int*   sq   = (int*)(arow + QB);
    int*   sk   = sq + QB;

    const int qb = blockIdx.x;
    const int h  = blockIdx.y;
    const int kh = h >> 2;
    const int tid = threadIdx.x;
    const int tx = tid & 15, ty = tid >> 4;
    const int ty4 = ty * 4;

#pragma unroll
    for (int i = 0; i < 8; i++) {
        int lin = tid + i * 256;
        int r = lin >> 5;
        int c4 = (lin & 31) * 4;
        float4 v = *(const float4*)(Q + ((size_t)(qb * QB + r) * NH + h) * HD + c4);
        Qs[r * KSTR + c4 + 0] = v.x; Qs[r * KSTR + c4 + 1] = v.y;
        Qs[r * KSTR + c4 + 2] = v.z; Qs[r * KSTR + c4 + 3] = v.w;
    }
    if (tid < QB) {
        sq[tid]   = sid[qb * QB + tid];
        mrow[tid] = -3.0e38f;
        lrow[tid] = 0.f;
    }
    __syncthreads();
    const int sq_first = sq[0];

    float acc[4][8];
#pragma unroll
    for (int i = 0; i < 4; i++)
#pragma unroll
        for (int j = 0; j < 8; j++) acc[i][j] = 0.f;

    const float scale = 0.08838834764831845f;

    for (int kb = 0; kb <= qb; kb++) {
        if (sid[kb * KBLK + KBLK - 1] < sq_first) continue;

        __syncthreads();

#pragma unroll
        for (int i = 0; i < 8; i++) {
            int lin = tid + i * 256;
            int r = lin >> 5;
            int c4 = (lin & 31) * 4;
            size_t goff = ((size_t)(kb * KBLK + r) * NKV + kh) * HD + c4;
            float4 kv = *(const float4*)(K + goff);
            Ks[r * KSTR + c4 + 0] = kv.x; Ks[r * KSTR + c4 + 1] = kv.y;
            Ks[r * KSTR + c4 + 2] = kv.z; Ks[r * KSTR + c4 + 3] = kv.w;
            float4 vv = *(const float4*)(V + goff);
            Vs[r * KSTR + c4 + 0] = vv.x; Vs[r * KSTR + c4 + 1] = vv.y;
            Vs[r * KSTR + c4 + 2] = vv.z; Vs[r * KSTR + c4 + 3] = vv.w;
        }
        if (tid < KBLK) sk[tid] = sid[kb * KBLK + tid];
        __syncthreads();

        float s[4][4];
#pragma unroll
        for (int i = 0; i < 4; i++)
#pragma unroll
            for (int j = 0; j < 4; j++) s[i][j] = 0.f;

#pragma unroll 4
        for (int d = 0; d < HD; d++) {
            float q0 = Qs[(ty4 + 0) * KSTR + d];
            float q1 = Qs[(ty4 + 1) * KSTR + d];
            float q2 = Qs[(ty4 + 2) * KSTR + d];
            float q3 = Qs[(ty4 + 3) * KSTR + d];
            float k0 = Ks[(tx +  0) * KSTR + d];
            float k1 = Ks[(tx + 16) * KSTR + d];
            float k2 = Ks[(tx + 32) * KSTR + d];
            float k3 = Ks[(tx + 48) * KSTR + d];
            s[0][0] = fmaf(q0, k0, s[0][0]); s[0][1] = fmaf(q0, k1, s[0][1]);
            s[0][2] = fmaf(q0, k2, s[0][2]); s[0][3] = fmaf(q0, k3, s[0][3]);
            s[1][0] = fmaf(q1, k0, s[1][0]); s[1][1] = fmaf(q1, k1, s[1][1]);
            s[1][2] = fmaf(q1, k2, s[1][2]); s[1][3] = fmaf(q1, k3, s[1][3]);
            s[2][0] = fmaf(q2, k0, s[2][0]); s[2][1] = fmaf(q2, k1, s[2][1]);
            s[2][2] = fmaf(q2, k2, s[2][2]); s[2][3] = fmaf(q2, k3, s[2][3]);
            s[3][0] = fmaf(q3, k0, s[3][0]); s[3][1] = fmaf(q3, k1, s[3][1]);
            s[3][2] = fmaf(q3, k2, s[3][2]); s[3][3] = fmaf(q3, k3, s[3][3]);
        }

        const int qi0 = qb * QB, ki0 = kb * KBLK;
#pragma unroll
        for (int i = 0; i < 4; i++) {
            int r = ty4 + i;
            int qi = qi0 + r;
            int sqr = sq[r];
#pragma unroll
            for (int j = 0; j < 4; j++) {
                int c = tx + 16 * j;
                int ki = ki0 + c;
                float val = s[i][j] * scale;
                if (ki > qi || sk[c] != sqr) val = -1.0e30f;
                Ss[r * SSTR + c] = val;
            }
        }
        __syncthreads();

        {
            int r = tid >> 2, l4 = tid & 3;
            float mx = -3.0e38f;
            for (int c = l4; c < KBLK; c += 4) mx = fmaxf(mx, Ss[r * SSTR + c]);
            mx = fmaxf(mx, __shfl_xor_sync(0xffffffffu, mx, 1));
            mx = fmaxf(mx, __shfl_xor_sync(0xffffffffu, mx, 2));
            float mold = mrow[r];
            float mnew = fmaxf(mold, mx);
            float sum = 0.f;
            for (int c = l4; c < KBLK; c += 4) {
                float p = __expf(Ss[r * SSTR + c] - mnew);
                Ss[r * SSTR + c] = p;
                sum += p;
            }
            sum += __shfl_xor_sync(0xffffffffu, sum, 1);
            sum += __shfl_xor_sync(0xffffffffu, sum, 2);
            if (l4 == 0) {
                float al = __expf(mold - mnew);
                arow[r] = al;
                lrow[r] = lrow[r] * al + sum;
                mrow[r] = mnew;
            }
        }
        __syncthreads();

        {
            float al0 = arow[ty4 + 0], al1 = arow[ty4 + 1];
            float al2 = arow[ty4 + 2], al3 = arow[ty4 + 3];
#pragma unroll
            for (int j = 0; j < 8; j++) {
                acc[0][j] *= al0; acc[1][j] *= al1;
                acc[2][j] *= al2; acc[3][j] *= al3;
            }
#pragma unroll 2
            for (int k = 0; k < KBLK; k++) {
                float p0 = Ss[(ty4 + 0) * SSTR + k];
                float p1 = Ss[(ty4 + 1) * SSTR + k];
                float p2 = Ss[(ty4 + 2) * SSTR + k];
                float p3 = Ss[(ty4 + 3) * SSTR + k];
#pragma unroll
                for (int j = 0; j < 8; j++) {
                    float v = Vs[k * KSTR + tx + 16 * j];
                    acc[0][j] = fmaf(p0, v, acc[0][j]);
                    acc[1][j] = fmaf(p1, v, acc[1][j]);
                    acc[2][j] = fmaf(p2, v, acc[2][j]);
                    acc[3][j] = fmaf(p3, v, acc[3][j]);
                }
            }
        }
    }

#pragma unroll
    for (int i = 0; i < 4; i++) {
        int r = ty4 + i;
        float inv = 1.0f / lrow[r];
        size_t base = ((size_t)(qb * QB + r) * NH + h) * HD;
#pragma unroll
        for (int j = 0; j < 8; j++)
            Aout[base + tx + 16 * j] = acc[i][j] * inv;
    }
}

// ----------------------------------------------------------------
extern "C" void kernel_launch(void* const* d_in, const int* in_sizes, int n_in,
                              void* d_out, int out_size)
{
    const float* x   = (const float*)d_in[0];
    const float* wq  = (const float*)d_in[1];
    const float* wk  = (const float*)d_in[2];
    const float* wv  = (const float*)d_in[3];
    const float* wo  = (const float*)d_in[4];
    const float* fc  = (const float*)d_in[5];
    const float* fs  = (const float*)d_in[6];
    const int*   sid = (const int*)d_in[7];
    float* out = (float*)d_out;

    float *Qp, *Kp, *Vp, *Ap;
    __half *xh, *xl, *ah, *al, *wqkvh, *wqkvl, *woh, *wol;
    cudaGetSymbolAddress((void**)&Qp, g_Q);
    cudaGetSymbolAddress((void**)&Kp, g_K);
    cudaGetSymbolAddress((void**)&Vp, g_V);
    cudaGetSymbolAddress((void**)&Ap, g_A);
    cudaGetSymbolAddress((void**)&xh, g_xh);
    cudaGetSymbolAddress((void**)&xl, g_xl);
    cudaGetSymbolAddress((void**)&ah, g_ah);
    cudaGetSymbolAddress((void**)&al, g_al);
    cudaGetSymbolAddress((void**)&wqkvh, g_wqkvh);
    cudaGetSymbolAddress((void**)&wqkvl, g_wqkvl);
    cudaGetSymbolAddress((void**)&woh, g_woh);
    cudaGetSymbolAddress((void**)&wol, g_wol);

    cudaFuncSetAttribute(gemm_hmma, cudaFuncAttributeMaxDynamicSharedMemorySize, GEMM_SMEM);

    // split x; transpose+split weights
    pack_split<<<(T_TOK * DIM / 4 + 255) / 256, 256>>>(x, xh, xl, T_TOK * DIM / 4);
    pack_wT<<<dim3(DIM / 32, 2048 / 32), 256>>>(wq, wqkvh, wqkvl, 2048, 0);
    pack_wT<<<dim3(DIM / 32,  512 / 32), 256>>>(wk, wqkvh, wqkvl, 512, 2048);
    pack_wT<<<dim3(DIM / 32,  512 / 32), 256>>>(wv, wqkvh, wqkvl, 512, 2560);
    pack_wT<<<dim3(DIM / 32, 2048 / 32), 256>>>(wo, woh, wol, 2048, 0);

    // fused QKV projection (N = 3072)
    gemm_hmma<<<dim3(3072 / BN, T_TOK / BM), 128, GEMM_SMEM>>>(
        xh, xl, wqkvh, wqkvl, Qp, Kp, Vp);

    // RoPE
    rope_kernel<<<(T_TOK * (NH + NKV) * 64) / 256, 256>>>(Qp, Kp, fc, fs);

    // Flash attention
    size_t smem = (size_t)(3 * QB * KSTR + QB * SSTR + 3 * QB) * sizeof(float)
                + (size_t)(2 * QB) * sizeof(int);
    cudaFuncSetAttribute(flash_kernel, cudaFuncAttributeMaxDynamicSharedMemorySize, (int)smem);
    flash_kernel<<<dim3(T_TOK / QB, NH), 256, smem>>>(Qp, Kp, Vp, sid, Ap);

    // output projection
    pack_split<<<(T_TOK * DIM / 4 + 255) / 256, 256>>>(Ap, ah, al, T_TOK * DIM / 4);
    gemm_hmma<<<dim3(DIM / BN, T_TOK / BM), 128, GEMM_SMEM>>>(
        ah, al, woh, wol, out, nullptr, nullptr);
}

// round 8
// speedup vs baseline: 2.6030x; 1.4671x over previous
#include <cuda_runtime.h>
#include <cuda_fp16.h>
#include <cstdint>
#include <math.h>

// ---------------- problem constants ----------------
#define T_TOK   4096
#define DIM     2048
#define NH      16
#define NKV     4
#define HD      128

// ---------------- HMMA GEMM constants ----------------
#define BM 128
#define BN 128
#define BK 32
#define PADK 40
#define MAT_BYTES (128 * PADK * 2)
#define STAGE_B   (4 * MAT_BYTES)
#define NSTAGE 3
#define GEMM_SMEM (NSTAGE * STAGE_B)

// ---------------- flash constants ----------------
#define FQB  128                     // q rows per block
#define FKB  64                      // k tokens per tile
#define KROW 136                     // halves per row (Q/K tiles)
#define VROW 72                      // halves per row (Vt tiles)
#define QL_H   (FQB * KROW)          // 17408
#define STG0_H (2 * FQB * KROW)      // 34816
#define KL_H   (FKB * KROW)          // 8704
#define VH_H   (2 * FKB * KROW)      // 17408
#define VL_H   (VH_H + HD * VROW)    // 26624
#define STG_H  (VL_H + HD * VROW)    // 35840
#define FLASH_SMEM ((STG0_H + 2 * STG_H) * 2)   // 212992 B

extern __shared__ __align__(16) char dyn_smem[];

// -------- scratch (device globals) --------
__device__ float g_Q[T_TOK * NH * HD];
__device__ float g_K[T_TOK * NKV * HD];
__device__ float g_V[T_TOK * NKV * HD];
__device__ float g_A[T_TOK * NH * HD];
__device__ __half g_xh[T_TOK * DIM],  g_xl[T_TOK * DIM];
__device__ __half g_ah[T_TOK * DIM],  g_al[T_TOK * DIM];
__device__ __half g_wqkvh[3072 * DIM], g_wqkvl[3072 * DIM];
__device__ __half g_woh[DIM * DIM],   g_wol[DIM * DIM];
__device__ __half g_qh[T_TOK * NH * HD],  g_ql[T_TOK * NH * HD];
__device__ __half g_kh[T_TOK * NKV * HD], g_kl[T_TOK * NKV * HD];
__device__ __half g_vth[NKV * HD * T_TOK], g_vtl[NKV * HD * T_TOK];  // [kv][d][tok]

// ---------------- helpers ----------------
__device__ __forceinline__ void cp16(void* dst, const void* src) {
    uint32_t d;
    asm("{ .reg .u64 t; cvta.to.shared.u64 t, %1; cvt.u32.u64 %0, t; }" : "=r"(d) : "l"(dst));
    asm volatile("cp.async.cg.shared.global [%0], [%1], 16;" :: "r"(d), "l"(src));
}
__device__ __forceinline__ void mma16816(float* c, const uint32_t* a, const uint32_t* b) {
    asm volatile(
        "mma.sync.aligned.m16n8k16.row.col.f32.f16.f16.f32 "
        "{%0,%1,%2,%3}, {%4,%5,%6,%7}, {%8,%9}, {%0,%1,%2,%3};"
        : "+f"(c[0]), "+f"(c[1]), "+f"(c[2]), "+f"(c[3])
        : "r"(a[0]), "r"(a[1]), "r"(a[2]), "r"(a[3]), "r"(b[0]), "r"(b[1]));
}

// ---------------- pack: fp32 -> (hi, lo) fp16 ----------------
__global__ void __launch_bounds__(256) pack_split(const float* __restrict__ in,
                                                  __half* __restrict__ oh,
                                                  __half* __restrict__ ol, int n4) {
    int i = blockIdx.x * blockDim.x + threadIdx.x;
    if (i >= n4) return;
    float4 v = ((const float4*)in)[i];
    __half h0 = __float2half_rn(v.x), h1 = __float2half_rn(v.y);
    __half h2 = __float2half_rn(v.z), h3 = __float2half_rn(v.w);
    __half l0 = __float2half_rn(v.x - __half2float(h0));
    __half l1 = __float2half_rn(v.y - __half2float(h1));
    __half l2 = __float2half_rn(v.z - __half2float(h2));
    __half l3 = __float2half_rn(v.w - __half2float(h3));
    ((__half2*)oh)[i * 2 + 0] = __halves2half2(h0, h1);
    ((__half2*)oh)[i * 2 + 1] = __halves2half2(h2, h3);
    ((__half2*)ol)[i * 2 + 0] = __halves2half2(l0, l1);
    ((__half2*)ol)[i * 2 + 1] = __halves2half2(l2, l3);
}

// ---------------- pack: w[K][Nsrc] -> transposed [nbase+n][K] hi/lo ----------------
__global__ void __launch_bounds__(256) pack_wT(const float* __restrict__ w,
                                               __half* __restrict__ oh,
                                               __half* __restrict__ ol,
                                               int Nsrc, int nbase) {
    __shared__ float t[32][33];
    int k0 = blockIdx.x * 32, n0 = blockIdx.y * 32;
    int tid = threadIdx.x;
    int cc = tid & 31, rr = tid >> 5;
#pragma unroll
    for (int i = 0; i < 4; i++) {
        int row = rr + i * 8;
        t[row][cc] = w[(size_t)(k0 + row) * Nsrc + n0 + cc];
    }
    __syncthreads();
#pragma unroll
    for (int i = 0; i < 4; i++) {
        int n = rr + i * 8;
        float v = t[cc][n];
        __half h = __float2half_rn(v);
        __half l = __float2half_rn(v - __half2float(h));
        size_t o = (size_t)(nbase + n0 + n) * DIM + k0 + cc;
        oh[o] = h;
        ol[o] = l;
    }
}

// ---------------- HMMA GEMM (unchanged from R7) ----------------
__global__ void __launch_bounds__(128, 1) gemm_hmma(const __half* __restrict__ Ah,
                                                    const __half* __restrict__ Al,
                                                    const __half* __restrict__ Bh,
                                                    const __half* __restrict__ Bl,
                                                    float* __restrict__ Cq,
                                                    float* __restrict__ Ck,
                                                    float* __restrict__ Cv) {
    char* sm = dyn_smem;
    const int tid = threadIdx.x;
    const int wid = tid >> 5, lane = tid & 31;
    const int wm = (wid & 1) * 64, wn = (wid >> 1) * 64;
    const int lg = lane >> 2, lt = lane & 3;

    const size_t arow0 = (size_t)blockIdx.y * BM;
    const size_t brow0 = (size_t)blockIdx.x * BN;

    float acc[4][8][4];
#pragma unroll
    for (int mf = 0; mf < 4; mf++)
#pragma unroll
        for (int nf = 0; nf < 8; nf++)
#pragma unroll
            for (int q = 0; q < 4; q++) acc[mf][nf][q] = 0.f;

    const int NKT = DIM / BK;

#define G_ISSUE(KT, ST) do {                                                     \
    char* _sb = sm + (ST) * STAGE_B;                                             \
    int _k0 = (KT) * BK;                                                         \
    _Pragma("unroll")                                                            \
    for (int _i = 0; _i < 16; _i++) {                                            \
        int _idx = tid + _i * 128;                                               \
        int _mat = _idx >> 9;                                                    \
        int _rem = _idx & 511;                                                   \
        int _row = _rem >> 2;                                                    \
        int _ch  = _rem & 3;                                                     \
        const __half* _src;                                                      \
        if (_mat == 0)      _src = Ah + (arow0 + _row) * DIM + _k0 + _ch * 8;    \
        else if (_mat == 1) _src = Al + (arow0 + _row) * DIM + _k0 + _ch * 8;    \
        else if (_mat == 2) _src = Bh + (brow0 + _row) * DIM + _k0 + _ch * 8;    \
        else                _src = Bl + (brow0 + _row) * DIM + _k0 + _ch * 8;    \
        cp16(_sb + _mat * MAT_BYTES + _row * 80 + _ch * 16, _src);               \
    }                                                                            \
    asm volatile("cp.async.commit_group;" ::: "memory");                         \
} while (0)

    G_ISSUE(0, 0);
    G_ISSUE(1, 1);

    for (int kt = 0; kt < NKT; kt++) {
        int st = kt % NSTAGE;
        if (kt + 1 < NKT) asm volatile("cp.async.wait_group 1;" ::: "memory");
        else              asm volatile("cp.async.wait_group 0;" ::: "memory");
        __syncthreads();
        if (kt + 2 < NKT) G_ISSUE(kt + 2, (kt + 2) % NSTAGE);

        const uint32_t* sAh = (const uint32_t*)(sm + st * STAGE_B);
        const uint32_t* sAl = sAh + MAT_BYTES / 4;
        const uint32_t* sBh = sAl + MAT_BYTES / 4;
        const uint32_t* sBl = sBh + MAT_BYTES / 4;

#pragma unroll
        for (int ks = 0; ks < 2; ks++) {
            uint32_t ah[4][4], al[4][4];
            const int cb = lt + ks * 8;
#pragma unroll
            for (int mf = 0; mf < 4; mf++) {
                int r0 = (wm + mf * 16 + lg) * (PADK / 2);
                int r1 = r0 + 8 * (PADK / 2);
                ah[mf][0] = sAh[r0 + cb];     ah[mf][1] = sAh[r1 + cb];
                ah[mf][2] = sAh[r0 + cb + 4]; ah[mf][3] = sAh[r1 + cb + 4];
                al[mf][0] = sAl[r0 + cb];     al[mf][1] = sAl[r1 + cb];
                al[mf][2] = sAl[r0 + cb + 4]; al[mf][3] = sAl[r1 + cb + 4];
            }
#pragma unroll
            for (int nf = 0; nf < 8; nf++) {
                int nr = (wn + nf * 8 + lg) * (PADK / 2);
                uint32_t bh[2], bl[2];
                bh[0] = sBh[nr + cb]; bh[1] = sBh[nr + cb + 4];
                bl[0] = sBl[nr + cb]; bl[1] = sBl[nr + cb + 4];
#pragma unroll
                for (int mf = 0; mf < 4; mf++) {
                    mma16816(acc[mf][nf], ah[mf], bh);
                    mma16816(acc[mf][nf], ah[mf], bl);
                    mma16816(acc[mf][nf], al[mf], bh);
                }
            }
        }
    }

    float* Cb;
    int stride, colofs;
    int nblock = blockIdx.x * BN;
    if (Ck == nullptr || nblock < 2048) { Cb = Cq; stride = 2048; colofs = nblock; }
    else if (nblock < 2560)             { Cb = Ck; stride = 512;  colofs = nblock - 2048; }
    else                                { Cb = Cv; stride = 512;  colofs = nblock - 2560; }

#pragma unroll
    for (int mf = 0; mf < 4; mf++) {
        size_t row0 = arow0 + wm + mf * 16 + lg;
#pragma unroll
        for (int nf = 0; nf < 8; nf++) {
            int col = colofs + wn + nf * 8 + lt * 2;
            *(float2*)(Cb + row0 * stride + col) =
                make_float2(acc[mf][nf][0], acc[mf][nf][1]);
            *(float2*)(Cb + (row0 + 8) * stride + col) =
                make_float2(acc[mf][nf][2], acc[mf][nf][3]);
        }
    }
}

// ---------------- RoPE + hi/lo split of Q, K ----------------
__global__ void rope_split(const float* __restrict__ Q, const float* __restrict__ K,
                           const float* __restrict__ fcos, const float* __restrict__ fsin,
                           __half* __restrict__ qh, __half* __restrict__ ql,
                           __half* __restrict__ kh, __half* __restrict__ kl)
{
    int idx = blockIdx.x * blockDim.x + threadIdx.x;
    int pair = idx & 63;
    int rest = idx >> 6;
    int h = rest % (NH + NKV);
    int t = rest / (NH + NKV);
    float c = fcos[t * 64 + pair];
    float s = fsin[t * 64 + pair];
    const float* p;
    size_t off;
    __half *oh, *ol;
    if (h < NH) {
        off = ((size_t)t * NH + h) * HD + pair * 2;
        p = Q + off; oh = qh; ol = ql;
    } else {
        off = ((size_t)t * NKV + (h - NH)) * HD + pair * 2;
        p = K + off; oh = kh; ol = kl;
    }
    float x0 = p[0], x1 = p[1];
    float o0 = x0 * c - x1 * s;
    float o1 = x0 * s + x1 * c;
    __half h0 = __float2half_rn(o0);
    __half h1 = __float2half_rn(o1);
    oh[off]     = h0;
    oh[off + 1] = h1;
    ol[off]     = __float2half_rn(o0 - __half2float(h0));
    ol[off + 1] = __float2half_rn(o1 - __half2float(h1));
}

// ---------------- V: fp32 [tok][kv][HD] -> fp16 hi/lo transposed [kv][d][tok] ----------------
__global__ void __launch_bounds__(256) transpose_v(const float* __restrict__ V,
                                                   __half* __restrict__ vth,
                                                   __half* __restrict__ vtl)
{
    __shared__ float t[32][33];
    int kv = blockIdx.z, t0 = blockIdx.x * 32, d0 = blockIdx.y * 32;
    int cc = threadIdx.x & 31, rr = threadIdx.x >> 5;
#pragma unroll
    for (int i = 0; i < 4; i++) {
        int tok = rr + i * 8;
        t[tok][cc] = V[((size_t)(t0 + tok) * NKV + kv) * HD + d0 + cc];
    }
    __syncthreads();
#pragma unroll
    for (int i = 0; i < 4; i++) {
        int dd = rr + i * 8;
        float v = t[cc][dd];
        __half h = __float2half_rn(v);
        size_t o = ((size_t)kv * HD + d0 + dd) * T_TOK + t0 + cc;
        vth[o] = h;
        vtl[o] = __float2half_rn(v - __half2float(h));
    }
}

// ---------------- flash attention on HMMA, fp16x3 ----------------
__global__ void __launch_bounds__(256) flash_hmma(
    const __half* __restrict__ qh, const __half* __restrict__ ql,
    const __half* __restrict__ kh, const __half* __restrict__ kl,
    const __half* __restrict__ vth, const __half* __restrict__ vtl,
    const int* __restrict__ sid, float* __restrict__ Aout)
{
    __half* S = (__half*)dyn_smem;
    const int tid = threadIdx.x, wid = tid >> 5, lane = tid & 31;
    const int lg = lane >> 2, lt = lane & 3;
    const int h = blockIdx.y, kv = h >> 2;
    const int q0 = blockIdx.x * FQB;

    // issue Q tile (hi+lo): 128 rows x 16 chunks x 2 splits = 4096 chunks
#pragma unroll
    for (int i = 0; i < 16; i++) {
        int id = tid + i * 256;
        int sp = id >> 11, rem = id & 2047;
        int row = rem >> 4, ch = rem & 15;
        const __half* src = (sp ? ql : qh) + ((size_t)(q0 + row) * NH + h) * HD + ch * 8;
        cp16(S + sp * QL_H + row * KROW + ch * 8, src);
    }
    asm volatile("cp.async.commit_group;" ::: "memory");

#define F_ISSUE(KB, ST) do {                                                          \
    __half* _s = S + STG0_H + (ST) * STG_H;                                           \
    int _t0 = (KB) * FKB;                                                             \
    _Pragma("unroll")                                                                 \
    for (int _i = 0; _i < 8; _i++) {       /* K: 2 splits x 64 rows x 16 ch */        \
        int _id = tid + _i * 256;                                                     \
        int _sp = _id >> 10, _rem = _id & 1023;                                       \
        int _row = _rem >> 4, _ch = _rem & 15;                                        \
        const __half* _src = (_sp ? kl : kh)                                          \
            + ((size_t)(_t0 + _row) * NKV + kv) * HD + _ch * 8;                       \
        cp16(_s + _sp * KL_H + _row * KROW + _ch * 8, _src);                          \
    }                                                                                 \
    _Pragma("unroll")                                                                 \
    for (int _i = 0; _i < 8; _i++) {       /* Vt: 2 splits x 128 rows x 8 ch */       \
        int _id = tid + _i * 256;                                                     \
        int _sp = _id >> 10, _rem = _id & 1023;                                       \
        int _row = _rem >> 3, _ch = _rem & 7;                                         \
        const __half* _src = (_sp ? vtl : vth)                                        \
            + ((size_t)kv * HD + _row) * T_TOK + _t0 + _ch * 8;                       \
        cp16(_s + VH_H + _sp * (HD * VROW) + _row * VROW + _ch * 8, _src);            \
    }                                                                                 \
    asm volatile("cp.async.commit_group;" ::: "memory");                              \
} while (0)

    const int qi0 = q0 + wid * 16 + lg, qi1 = qi0 + 8;
    const int sqr0 = sid[qi0], sqr1 = sid[qi1];
    const int sq_first = sid[q0];
    const int kbe = q0 / FKB + 1;           // last kb tile index
    int kb0 = kbe;
    for (int kb = 0; kb <= kbe; kb++) {
        if (sid[kb * FKB + FKB - 1] >= sq_first) { kb0 = kb; break; }
    }

    F_ISSUE(kb0, 0);
    if (kb0 + 1 <= kbe) F_ISSUE(kb0 + 1, 1);

    float o[16][4];
#pragma unroll
    for (int i = 0; i < 16; i++)
#pragma unroll
        for (int j = 0; j < 4; j++) o[i][j] = 0.f;
    float m0 = -1.0e30f, l0 = 0.f, m1 = -1.0e30f, l1 = 0.f;

    const float scale = 0.08838834764831845f;
    const uint32_t* Qu  = (const uint32_t*)S;
    const uint32_t* Qlu = Qu + QL_H / 2;
    const int ar0 = (wid * 16 + lg) * (KROW / 2), ar1 = ar0 + 8 * (KROW / 2);

    for (int kb = kb0; kb <= kbe; kb++) {
        int st = (kb - kb0) & 1;
        if (kb + 1 <= kbe) asm volatile("cp.async.wait_group 1;" ::: "memory");
        else               asm volatile("cp.async.wait_group 0;" ::: "memory");
        __syncthreads();

        const uint32_t* Ku  = (const uint32_t*)(S + STG0_H + st * STG_H);
        const uint32_t* Klu = Ku + KL_H / 2;
        const uint32_t* Vu  = (const uint32_t*)(S + STG0_H + st * STG_H + VH_H);
        const uint32_t* Vlu = Vu + (HD * VROW) / 2;

        // ---- S = Q K^T (fp16x3) ----
        float sf[8][4];
#pragma unroll
        for (int nf = 0; nf < 8; nf++)
#pragma unroll
            for (int q = 0; q < 4; q++) sf[nf][q] = 0.f;

#pragma unroll
        for (int ks = 0; ks < 8; ks++) {
            const int ko = ks * 8 + lt;
            uint32_t ah[4], al[4];
            ah[0] = Qu[ar0 + ko];  ah[1] = Qu[ar1 + ko];
            ah[2] = Qu[ar0 + ko + 4]; ah[3] = Qu[ar1 + ko + 4];
            al[0] = Qlu[ar0 + ko]; al[1] = Qlu[ar1 + ko];
            al[2] = Qlu[ar0 + ko + 4]; al[3] = Qlu[ar1 + ko + 4];
#pragma unroll
            for (int nf = 0; nf < 8; nf++) {
                int br = (nf * 8 + lg) * (KROW / 2);
                uint32_t bh[2], bl2[2];
                bh[0] = Ku[br + ko];  bh[1] = Ku[br + ko + 4];
                bl2[0] = Klu[br + ko]; bl2[1] = Klu[br + ko + 4];
                mma16816(sf[nf], ah, bh);
                mma16816(sf[nf], al, bh);
                mma16816(sf[nf], ah, bl2);
            }
        }

        // ---- mask + scale ----
        const int kbase = kb * FKB;
#pragma unroll
        for (int nf = 0; nf < 8; nf++) {
            int c0 = kbase + nf * 8 + lt * 2;
            int sk0 = sid[c0], sk1 = sid[c0 + 1];
            sf[nf][0] = (c0 > qi0     || sk0 != sqr0) ? -1.0e30f : sf[nf][0] * scale;
            sf[nf][1] = (c0 + 1 > qi0 || sk1 != sqr0) ? -1.0e30f : sf[nf][1] * scale;
            sf[nf][2] = (c0 > qi1     || sk0 != sqr1) ? -1.0e30f : sf[nf][2] * scale;
            sf[nf][3] = (c0 + 1 > qi1 || sk1 != sqr1) ? -1.0e30f : sf[nf][3] * scale;
        }

        // ---- online softmax ----
        float mx0 = -1.0e30f, mx1 = -1.0e30f;
#pragma unroll
        for (int nf = 0; nf < 8; nf++) {
            mx0 = fmaxf(mx0, fmaxf(sf[nf][0], sf[nf][1]));
            mx1 = fmaxf(mx1, fmaxf(sf[nf][2], sf[nf][3]));
        }
        mx0 = fmaxf(mx0, __shfl_xor_sync(0xffffffffu, mx0, 1));
        mx0 = fmaxf(mx0, __shfl_xor_sync(0xffffffffu, mx0, 2));
        mx1 = fmaxf(mx1, __shfl_xor_sync(0xffffffffu, mx1, 1));
        mx1 = fmaxf(mx1, __shfl_xor_sync(0xffffffffu, mx1, 2));
        float mn0 = fmaxf(m0, mx0), mn1 = fmaxf(m1, mx1);
        float a0 = __expf(m0 - mn0), a1 = __expf(m1 - mn1);
        float sum0 = 0.f, sum1 = 0.f;
        uint32_t ph[4][4], pl[4][4];
#pragma unroll
        for (int nf = 0; nf < 8; nf++) {
            float p0 = __expf(sf[nf][0] - mn0);
            float p1 = __expf(sf[nf][1] - mn0);
            float p2 = __expf(sf[nf][2] - mn1);
            float p3 = __expf(sf[nf][3] - mn1);
            sum0 += p0 + p1; sum1 += p2 + p3;
            __half2 h01 = __floats2half2_rn(p0, p1);
            float2 f01 = __half22float2(h01);
            __half2 e01 = __floats2half2_rn(p0 - f01.x, p1 - f01.y);
            __half2 h23 = __floats2half2_rn(p2, p3);
            float2 f23 = __half22float2(h23);
            __half2 e23 = __floats2half2_rn(p2 - f23.x, p3 - f23.y);
            int ksv = nf >> 1, up = (nf & 1) ? 2 : 0;
            ph[ksv][up + 0] = *(uint32_t*)&h01;
            ph[ksv][up + 1] = *(uint32_t*)&h23;
            pl[ksv][up + 0] = *(uint32_t*)&e01;
            pl[ksv][up + 1] = *(uint32_t*)&e23;
        }
        sum0 += __shfl_xor_sync(0xffffffffu, sum0, 1);
        sum0 += __shfl_xor_sync(0xffffffffu, sum0, 2);
        sum1 += __shfl_xor_sync(0xffffffffu, sum1, 1);
        sum1 += __shfl_xor_sync(0xffffffffu, sum1, 2);
        l0 = l0 * a0 + sum0; m0 = mn0;
        l1 = l1 * a1 + sum1; m1 = mn1;

        // ---- rescale O, then O += P V (fp16x3) ----
#pragma unroll
        for (int nf2 = 0; nf2 < 16; nf2++) {
            o[nf2][0] *= a0; o[nf2][1] *= a0;
            o[nf2][2] *= a1; o[nf2][3] *= a1;
        }
#pragma unroll
        for (int nf2 = 0; nf2 < 16; nf2++) {
            int vr = (nf2 * 8 + lg) * (VROW / 2);
#pragma unroll
            for (int ksv = 0; ksv < 4; ksv++) {
                uint32_t bh[2], bl2[2];
                bh[0] = Vu[vr + ksv * 8 + lt];  bh[1] = Vu[vr + ksv * 8 + 4 + lt];
                bl2[0] = Vlu[vr + ksv * 8 + lt]; bl2[1] = Vlu[vr + ksv * 8 + 4 + lt];
                mma16816(o[nf2], ph[ksv], bh);
                mma16816(o[nf2], pl[ksv], bh);
                mma16816(o[nf2], ph[ksv], bl2);
            }
        }

        __syncthreads();
        if (kb + 2 <= kbe) F_ISSUE(kb + 2, st);
    }

    // ---- epilogue ----
    float i0 = 1.0f / l0, i1 = 1.0f / l1;
    int r0 = q0 + wid * 16 + lg;
#pragma unroll
    for (int nf2 = 0; nf2 < 16; nf2++) {
        int col = nf2 * 8 + lt * 2;
        size_t b0 = ((size_t)r0 * NH + h) * HD + col;
        size_t b1 = ((size_t)(r0 + 8) * NH + h) * HD + col;
        *(float2*)(Aout + b0) = make_float2(o[nf2][0] * i0, o[nf2][1] * i0);
        *(float2*)(Aout + b1) = make_float2(o[nf2][2] * i1, o[nf2][3] * i1);
    }
}

// ----------------------------------------------------------------
extern "C" void kernel_launch(void* const* d_in, const int* in_sizes, int n_in,
                              void* d_out, int out_size)
{
    const float* x   = (const float*)d_in[0];
    const float* wq  = (const float*)d_in[1];
    const float* wk  = (const float*)d_in[2];
    const float* wv  = (const float*)d_in[3];
    const float* wo  = (const float*)d_in[4];
    const float* fc  = (const float*)d_in[5];
    const float* fs  = (const float*)d_in[6];
    const int*   sid = (const int*)d_in[7];
    float* out = (float*)d_out;

    float *Qp, *Kp, *Vp, *Ap;
    __half *xh, *xl, *ah, *al, *wqkvh, *wqkvl, *woh, *wol;
    __half *qhp, *qlp, *khp, *klp, *vthp, *vtlp;
    cudaGetSymbolAddress((void**)&Qp, g_Q);
    cudaGetSymbolAddress((void**)&Kp, g_K);
    cudaGetSymbolAddress((void**)&Vp, g_V);
    cudaGetSymbolAddress((void**)&Ap, g_A);
    cudaGetSymbolAddress((void**)&xh, g_xh);
    cudaGetSymbolAddress((void**)&xl, g_xl);
    cudaGetSymbolAddress((void**)&ah, g_ah);
    cudaGetSymbolAddress((void**)&al, g_al);
    cudaGetSymbolAddress((void**)&wqkvh, g_wqkvh);
    cudaGetSymbolAddress((void**)&wqkvl, g_wqkvl);
    cudaGetSymbolAddress((void**)&woh, g_woh);
    cudaGetSymbolAddress((void**)&wol, g_wol);
    cudaGetSymbolAddress((void**)&qhp, g_qh);
    cudaGetSymbolAddress((void**)&qlp, g_ql);
    cudaGetSymbolAddress((void**)&khp, g_kh);
    cudaGetSymbolAddress((void**)&klp, g_kl);
    cudaGetSymbolAddress((void**)&vthp, g_vth);
    cudaGetSymbolAddress((void**)&vtlp, g_vtl);

    cudaFuncSetAttribute(gemm_hmma, cudaFuncAttributeMaxDynamicSharedMemorySize, GEMM_SMEM);
    cudaFuncSetAttribute(flash_hmma, cudaFuncAttributeMaxDynamicSharedMemorySize, FLASH_SMEM);

    // packing
    pack_split<<<(T_TOK * DIM / 4 + 255) / 256, 256>>>(x, xh, xl, T_TOK * DIM / 4);
    pack_wT<<<dim3(DIM / 32, 2048 / 32), 256>>>(wq, wqkvh, wqkvl, 2048, 0);
    pack_wT<<<dim3(DIM / 32,  512 / 32), 256>>>(wk, wqkvh, wqkvl, 512, 2048);
    pack_wT<<<dim3(DIM / 32,  512 / 32), 256>>>(wv, wqkvh, wqkvl, 512, 2560);
    pack_wT<<<dim3(DIM / 32, 2048 / 32), 256>>>(wo, woh, wol, 2048, 0);

    // fused QKV projection
    gemm_hmma<<<dim3(3072 / BN, T_TOK / BM), 128, GEMM_SMEM>>>(
        xh, xl, wqkvh, wqkvl, Qp, Kp, Vp);

    // RoPE + split Q/K; transpose + split V
    rope_split<<<(T_TOK * (NH + NKV) * 64) / 256, 256>>>(Qp, Kp, fc, fs, qhp, qlp, khp, klp);
    transpose_v<<<dim3(T_TOK / 32, HD / 32, NKV), 256>>>(Vp, vthp, vtlp);

    // flash attention on tensor cores
    flash_hmma<<<dim3(T_TOK / FQB, NH), 256, FLASH_SMEM>>>(
        qhp, qlp, khp, klp, vthp, vtlp, sid, Ap);

    // output projection
    pack_split<<<(T_TOK * DIM / 4 + 255) / 256, 256>>>(Ap, ah, al, T_TOK * DIM / 4);
    gemm_hmma<<<dim3(DIM / BN, T_TOK / BM), 128, GEMM_SMEM>>>(
        ah, al, woh, wol, out, nullptr, nullptr);
}

// round 9
// speedup vs baseline: 3.0091x; 1.1560x over previous
#include <cuda_runtime.h>
#include <cuda_fp16.h>
#include <cstdint>
#include <math.h>

// ---------------- problem constants ----------------
#define T_TOK   4096
#define DIM     2048
#define NH      16
#define NKV     4
#define HD      128

// ---------------- HMMA GEMM constants (BM=256, BN=128, 8 warps) ----------------
#define BM 256
#define BN 128
#define BK 32
#define GPAD 40                       // halves per smem row
#define GAH 0                         // stage offsets in halves
#define GAL (256 * GPAD)              // 10240
#define GBH (2 * 256 * GPAD)          // 20480
#define GBL (GBH + 128 * GPAD)        // 25600
#define GSTG_H (GBH + 2 * 128 * GPAD) // 30720 halves
#define STAGE_B (GSTG_H * 2)          // 61440 B
#define NSTAGE 3
#define GEMM_SMEM (NSTAGE * STAGE_B)  // 184320 B

// ---------------- flash constants ----------------
#define FQB  128
#define FKB  64
#define KROW 136
#define VROW 72
#define QL_H   (FQB * KROW)
#define STG0_H (2 * FQB * KROW)
#define KL_H   (FKB * KROW)
#define VH_H   (2 * FKB * KROW)
#define STG_H  (VH_H + 2 * HD * VROW)
#define FLASH_SMEM ((STG0_H + 2 * STG_H) * 2)   // 212992 B

extern __shared__ __align__(16) char dyn_smem[];

// -------- scratch (device globals) --------
__device__ float g_Q[T_TOK * NH * HD];
__device__ float g_K[T_TOK * NKV * HD];
__device__ float g_V[T_TOK * NKV * HD];
__device__ float g_A[T_TOK * NH * HD];
__device__ __half g_xh[T_TOK * DIM],  g_xl[T_TOK * DIM];
__device__ __half g_ah[T_TOK * DIM],  g_al[T_TOK * DIM];
__device__ __half g_wqkvh[3072 * DIM], g_wqkvl[3072 * DIM];
__device__ __half g_woh[DIM * DIM],   g_wol[DIM * DIM];
__device__ __half g_qh[T_TOK * NH * HD],  g_ql[T_TOK * NH * HD];
__device__ __half g_kh[T_TOK * NKV * HD], g_kl[T_TOK * NKV * HD];
__device__ __half g_vth[NKV * HD * T_TOK], g_vtl[NKV * HD * T_TOK];

// ---------------- helpers ----------------
__device__ __forceinline__ uint32_t smem_u32(const void* p) {
    uint32_t a;
    asm("{ .reg .u64 t; cvta.to.shared.u64 t, %1; cvt.u32.u64 %0, t; }" : "=r"(a) : "l"(p));
    return a;
}
__device__ __forceinline__ void cp16(void* dst, const void* src) {
    uint32_t d;
    asm("{ .reg .u64 t; cvta.to.shared.u64 t, %1; cvt.u32.u64 %0, t; }" : "=r"(d) : "l"(dst));
    asm volatile("cp.async.cg.shared.global [%0], [%1], 16;" :: "r"(d), "l"(src));
}
__device__ __forceinline__ void mma16816(float* c, const uint32_t* a, const uint32_t* b) {
    asm volatile(
        "mma.sync.aligned.m16n8k16.row.col.f32.f16.f16.f32 "
        "{%0,%1,%2,%3}, {%4,%5,%6,%7}, {%8,%9}, {%0,%1,%2,%3};"
        : "+f"(c[0]), "+f"(c[1]), "+f"(c[2]), "+f"(c[3])
        : "r"(a[0]), "r"(a[1]), "r"(a[2]), "r"(a[3]), "r"(b[0]), "r"(b[1]));
}
#define LDSM4(R, a) \
    asm volatile("ldmatrix.sync.aligned.m8n8.x4.shared.b16 {%0,%1,%2,%3}, [%4];" \
        : "=r"((R)[0]), "=r"((R)[1]), "=r"((R)[2]), "=r"((R)[3]) : "r"(a))

// ---------------- pack: fp32 -> (hi, lo) fp16 ----------------
__global__ void __launch_bounds__(256) pack_split(const float* __restrict__ in,
                                                  __half* __restrict__ oh,
                                                  __half* __restrict__ ol, int n4) {
    int i = blockIdx.x * blockDim.x + threadIdx.x;
    if (i >= n4) return;
    float4 v = ((const float4*)in)[i];
    __half h0 = __float2half_rn(v.x), h1 = __float2half_rn(v.y);
    __half h2 = __float2half_rn(v.z), h3 = __float2half_rn(v.w);
    __half l0 = __float2half_rn(v.x - __half2float(h0));
    __half l1 = __float2half_rn(v.y - __half2float(h1));
    __half l2 = __float2half_rn(v.z - __half2float(h2));
    __half l3 = __float2half_rn(v.w - __half2float(h3));
    ((__half2*)oh)[i * 2 + 0] = __halves2half2(h0, h1);
    ((__half2*)oh)[i * 2 + 1] = __halves2half2(h2, h3);
    ((__half2*)ol)[i * 2 + 0] = __halves2half2(l0, l1);
    ((__half2*)ol)[i * 2 + 1] = __halves2half2(l2, l3);
}

// ---------------- pack: w[K][Nsrc] -> transposed [nbase+n][K] hi/lo ----------------
__global__ void __launch_bounds__(256) pack_wT(const float* __restrict__ w,
                                               __half* __restrict__ oh,
                                               __half* __restrict__ ol,
                                               int Nsrc, int nbase) {
    __shared__ float t[32][33];
    int k0 = blockIdx.x * 32, n0 = blockIdx.y * 32;
    int tid = threadIdx.x;
    int cc = tid & 31, rr = tid >> 5;
#pragma unroll
    for (int i = 0; i < 4; i++) {
        int row = rr + i * 8;
        t[row][cc] = w[(size_t)(k0 + row) * Nsrc + n0 + cc];
    }
    __syncthreads();
#pragma unroll
    for (int i = 0; i < 4; i++) {
        int n = rr + i * 8;
        float v = t[cc][n];
        __half h = __float2half_rn(v);
        __half l = __float2half_rn(v - __half2float(h));
        size_t o = (size_t)(nbase + n0 + n) * DIM + k0 + cc;
        oh[o] = h;
        ol[o] = l;
    }
}

// ---------------- HMMA GEMM: 256x128 tiles, 8 warps, ldmatrix ----------------
__global__ void __launch_bounds__(256, 1) gemm_hmma(const __half* __restrict__ Ah,
                                                    const __half* __restrict__ Al,
                                                    const __half* __restrict__ Bh,
                                                    const __half* __restrict__ Bl,
                                                    float* __restrict__ Cq,
                                                    float* __restrict__ Ck,
                                                    float* __restrict__ Cv) {
    __half* sm = (__half*)dyn_smem;
    const int tid = threadIdx.x;
    const int wid = tid >> 5, lane = tid & 31;
    const int wm = (wid & 3) * 64, wn = (wid >> 2) * 64;
    const int lg = lane >> 2, lt = lane & 3;

    const size_t arow0 = (size_t)blockIdx.y * BM;
    const size_t brow0 = (size_t)blockIdx.x * BN;

    float acc[4][8][4];
#pragma unroll
    for (int mf = 0; mf < 4; mf++)
#pragma unroll
        for (int nf = 0; nf < 8; nf++)
#pragma unroll
            for (int q = 0; q < 4; q++) acc[mf][nf][q] = 0.f;

    const int NKT = DIM / BK;

#define G_ISSUE(KT, ST) do {                                                     \
    __half* _sb = sm + (ST) * GSTG_H;                                            \
    int _k0 = (KT) * BK;                                                         \
    _Pragma("unroll")                                                            \
    for (int _i = 0; _i < 12; _i++) {                                            \
        int _idx = tid + _i * 256;      /* 0..3071 */                            \
        if (_idx < 2048) {                                                       \
            int _sp = _idx >> 10, _rem = _idx & 1023;                            \
            int _row = _rem >> 2, _ch = _rem & 3;                                \
            const __half* _src = (_sp ? Al : Ah)                                 \
                + (arow0 + _row) * DIM + _k0 + _ch * 8;                          \
            cp16(_sb + _sp * GAL + _row * GPAD + _ch * 8, _src);                 \
        } else {                                                                 \
            int _j = _idx - 2048;                                                \
            int _sp = _j >> 9, _rem = _j & 511;                                  \
            int _row = _rem >> 2, _ch = _rem & 3;                                \
            const __half* _src = (_sp ? Bl : Bh)                                 \
                + (brow0 + _row) * DIM + _k0 + _ch * 8;                          \
            cp16(_sb + GBH + _sp * (128 * GPAD) + _row * GPAD + _ch * 8, _src);  \
        }                                                                        \
    }                                                                            \
    asm volatile("cp.async.commit_group;" ::: "memory");                         \
} while (0)

    G_ISSUE(0, 0);
    G_ISSUE(1, 1);

    // per-warp invariant ldmatrix byte offsets (within stage, halves*2)
    const uint32_t smb = smem_u32(sm);
    const int a_row = (lane & 15);
    const int a_ch  = (lane >> 4) * 8;
    const int b_row = ((lane >> 4) & 1) * 8 + (lane & 7);
    const int b_ch  = ((lane >> 3) & 1) * 8;

    for (int kt = 0; kt < NKT; kt++) {
        int st = kt % NSTAGE;
        if (kt + 1 < NKT) asm volatile("cp.async.wait_group 1;" ::: "memory");
        else              asm volatile("cp.async.wait_group 0;" ::: "memory");
        __syncthreads();
        if (kt + 2 < NKT) G_ISSUE(kt + 2, (kt + 2) % NSTAGE);

        const uint32_t sb = smb + st * GSTG_H * 2;

#pragma unroll
        for (int ks = 0; ks < 2; ks++) {
            uint32_t ah[4][4], al[4][4];
#pragma unroll
            for (int mf = 0; mf < 4; mf++) {
                uint32_t ao = sb + ((wm + mf * 16 + a_row) * GPAD + ks * 16 + a_ch) * 2;
                LDSM4(ah[mf], ao);
                LDSM4(al[mf], ao + GAL * 2);
            }
#pragma unroll
            for (int np = 0; np < 4; np++) {
                uint32_t bo = sb + (GBH + (wn + np * 16 + b_row) * GPAD + ks * 16 + b_ch) * 2;
                uint32_t b4h[4], b4l[4];
                LDSM4(b4h, bo);
                LDSM4(b4l, bo + (128 * GPAD) * 2);
#pragma unroll
                for (int half = 0; half < 2; half++) {
                    const uint32_t* bh2 = b4h + half * 2;
                    const uint32_t* bl2 = b4l + half * 2;
                    int nf = np * 2 + half;
#pragma unroll
                    for (int mf = 0; mf < 4; mf++) {
                        mma16816(acc[mf][nf], ah[mf], bh2);
                        mma16816(acc[mf][nf], ah[mf], bl2);
                        mma16816(acc[mf][nf], al[mf], bh2);
                    }
                }
            }
        }
    }

    float* Cb;
    int stride, colofs;
    int nblock = blockIdx.x * BN;
    if (Ck == nullptr || nblock < 2048) { Cb = Cq; stride = 2048; colofs = nblock; }
    else if (nblock < 2560)             { Cb = Ck; stride = 512;  colofs = nblock - 2048; }
    else                                { Cb = Cv; stride = 512;  colofs = nblock - 2560; }

#pragma unroll
    for (int mf = 0; mf < 4; mf++) {
        size_t row0 = arow0 + wm + mf * 16 + lg;
#pragma unroll
        for (int nf = 0; nf < 8; nf++) {
            int col = colofs + wn + nf * 8 + lt * 2;
            *(float2*)(Cb + row0 * stride + col) =
                make_float2(acc[mf][nf][0], acc[mf][nf][1]);
            *(float2*)(Cb + (row0 + 8) * stride + col) =
                make_float2(acc[mf][nf][2], acc[mf][nf][3]);
        }
    }
}

// ---------------- RoPE + hi/lo split of Q, K ----------------
__global__ void rope_split(const float* __restrict__ Q, const float* __restrict__ K,
                           const float* __restrict__ fcos, const float* __restrict__ fsin,
                           __half* __restrict__ qh, __half* __restrict__ ql,
                           __half* __restrict__ kh, __half* __restrict__ kl)
{
    int idx = blockIdx.x * blockDim.x + threadIdx.x;
    int pair = idx & 63;
    int rest = idx >> 6;
    int h = rest % (NH + NKV);
    int t = rest / (NH + NKV);
    float c = fcos[t * 64 + pair];
    float s = fsin[t * 64 + pair];
    const float* p;
    size_t off;
    __half *oh, *ol;
    if (h < NH) {
        off = ((size_t)t * NH + h) * HD + pair * 2;
        p = Q + off; oh = qh; ol = ql;
    } else {
        off = ((size_t)t * NKV + (h - NH)) * HD + pair * 2;
        p = K + off; oh = kh; ol = kl;
    }
    float x0 = p[0], x1 = p[1];
    float o0 = x0 * c - x1 * s;
    float o1 = x0 * s + x1 * c;
    __half h0 = __float2half_rn(o0);
    __half h1 = __float2half_rn(o1);
    oh[off]     = h0;
    oh[off + 1] = h1;
    ol[off]     = __float2half_rn(o0 - __half2float(h0));
    ol[off + 1] = __float2half_rn(o1 - __half2float(h1));
}

// ---------------- V transpose + split ----------------
__global__ void __launch_bounds__(256) transpose_v(const float* __restrict__ V,
                                                   __half* __restrict__ vth,
                                                   __half* __restrict__ vtl)
{
    __shared__ float t[32][33];
    int kv = blockIdx.z, t0 = blockIdx.x * 32, d0 = blockIdx.y * 32;
    int cc = threadIdx.x & 31, rr = threadIdx.x >> 5;
#pragma unroll
    for (int i = 0; i < 4; i++) {
        int tok = rr + i * 8;
        t[tok][cc] = V[((size_t)(t0 + tok) * NKV + kv) * HD + d0 + cc];
    }
    __syncthreads();
#pragma unroll
    for (int i = 0; i < 4; i++) {
        int dd = rr + i * 8;
        float v = t[cc][dd];
        __half h = __float2half_rn(v);
        size_t o = ((size_t)kv * HD + d0 + dd) * T_TOK + t0 + cc;
        vth[o] = h;
        vtl[o] = __float2half_rn(v - __half2float(h));
    }
}

// ---------------- flash attention on HMMA, fp16x3, ldmatrix ----------------
__global__ void __launch_bounds__(256) flash_hmma(
    const __half* __restrict__ qh, const __half* __restrict__ ql,
    const __half* __restrict__ kh, const __half* __restrict__ kl,
    const __half* __restrict__ vth, const __half* __restrict__ vtl,
    const int* __restrict__ sid, float* __restrict__ Aout)
{
    __half* S = (__half*)dyn_smem;
    const int tid = threadIdx.x, wid = tid >> 5, lane = tid & 31;
    const int lg = lane >> 2, lt = lane & 3;
    const int h = blockIdx.y, kv = h >> 2;
    const int q0 = blockIdx.x * FQB;

#pragma unroll
    for (int i = 0; i < 16; i++) {
        int id = tid + i * 256;
        int sp = id >> 11, rem = id & 2047;
        int row = rem >> 4, ch = rem & 15;
        const __half* src = (sp ? ql : qh) + ((size_t)(q0 + row) * NH + h) * HD + ch * 8;
        cp16(S + sp * QL_H + row * KROW + ch * 8, src);
    }
    asm volatile("cp.async.commit_group;" ::: "memory");

#define F_ISSUE(KB, ST) do {                                                          \
    __half* _s = S + STG0_H + (ST) * STG_H;                                           \
    int _t0 = (KB) * FKB;                                                             \
    _Pragma("unroll")                                                                 \
    for (int _i = 0; _i < 8; _i++) {                                                  \
        int _id = tid + _i * 256;                                                     \
        int _sp = _id >> 10, _rem = _id & 1023;                                       \
        int _row = _rem >> 4, _ch = _rem & 15;                                        \
        const __half* _src = (_sp ? kl : kh)                                          \
            + ((size_t)(_t0 + _row) * NKV + kv) * HD + _ch * 8;                       \
        cp16(_s + _sp * KL_H + _row * KROW + _ch * 8, _src);                          \
    }                                                                                 \
    _Pragma("unroll")                                                                 \
    for (int _i = 0; _i < 8; _i++) {                                                  \
        int _id = tid + _i * 256;                                                     \
        int _sp = _id >> 10, _rem = _id & 1023;                                       \
        int _row = _rem >> 3, _ch = _rem & 7;                                         \
        const __half* _src = (_sp ? vtl : vth)                                        \
            + ((size_t)kv * HD + _row) * T_TOK + _t0 + _ch * 8;                       \
        cp16(_s + VH_H + _sp * (HD * VROW) + _row * VROW + _ch * 8, _src);            \
    }                                                                                 \
    asm volatile("cp.async.commit_group;" ::: "memory");                              \
} while (0)

    const int qi0 = q0 + wid * 16 + lg, qi1 = qi0 + 8;
    const int sqr0 = sid[qi0], sqr1 = sid[qi1];
    const int sq_first = sid[q0];
    const int kbe = q0 / FKB + 1;
    int kb0 = kbe;
    for (int kb = 0; kb <= kbe; kb++) {
        if (sid[kb * FKB + FKB - 1] >= sq_first) { kb0 = kb; break; }
    }

    F_ISSUE(kb0, 0);
    if (kb0 + 1 <= kbe) F_ISSUE(kb0 + 1, 1);

    float o[16][4];
#pragma unroll
    for (int i = 0; i < 16; i++)
#pragma unroll
        for (int j = 0; j < 4; j++) o[i][j] = 0.f;
    float m0 = -1.0e30f, l0 = 0.f, m1 = -1.0e30f, l1 = 0.f;

    const float scale = 0.08838834764831845f;
    const uint32_t Sb = smem_u32(S);

    // ldmatrix lane-invariant offsets
    const uint32_t q_off = Sb + (((wid * 16 + (lane & 15)) * KROW) + (lane >> 4) * 8) * 2;
    const int k_row = ((lane >> 4) & 1) * 8 + (lane & 7);
    const int k_ch  = ((lane >> 3) & 1) * 8;
    const int v_row = lane & 7;
    const int v_ch  = (lane >> 3) * 8;

    for (int kb = kb0; kb <= kbe; kb++) {
        int st = (kb - kb0) & 1;
        if (kb + 1 <= kbe) asm volatile("cp.async.wait_group 1;" ::: "memory");
        else               asm volatile("cp.async.wait_group 0;" ::: "memory");
        __syncthreads();

        const uint32_t Kb = Sb + (STG0_H + st * STG_H) * 2;
        const uint32_t Vb = Kb + VH_H * 2;

        // ---- S = Q K^T (fp16x3) ----
        float sf[8][4];
#pragma unroll
        for (int nf = 0; nf < 8; nf++)
#pragma unroll
            for (int q = 0; q < 4; q++) sf[nf][q] = 0.f;

#pragma unroll
        for (int ks = 0; ks < 8; ks++) {
            uint32_t ah[4], al[4];
            LDSM4(ah, q_off + ks * 32);
            LDSM4(al, q_off + ks * 32 + QL_H * 2);
#pragma unroll
            for (int np = 0; np < 4; np++) {
                uint32_t bo = Kb + ((np * 16 + k_row) * KROW + ks * 16 + k_ch) * 2;
                uint32_t b4h[4], b4l[4];
                LDSM4(b4h, bo);
                LDSM4(b4l, bo + KL_H * 2);
#pragma unroll
                for (int half = 0; half < 2; half++) {
                    int nf = np * 2 + half;
                    mma16816(sf[nf], ah, b4h + half * 2);
                    mma16816(sf[nf], al, b4h + half * 2);
                    mma16816(sf[nf], ah, b4l + half * 2);
                }
            }
        }

        // ---- mask + scale ----
        const int kbase = kb * FKB;
#pragma unroll
        for (int nf = 0; nf < 8; nf++) {
            int c0 = kbase + nf * 8 + lt * 2;
            int sk0 = sid[c0], sk1 = sid[c0 + 1];
            sf[nf][0] = (c0 > qi0     || sk0 != sqr0) ? -1.0e30f : sf[nf][0] * scale;
            sf[nf][1] = (c0 + 1 > qi0 || sk1 != sqr0) ? -1.0e30f : sf[nf][1] * scale;
            sf[nf][2] = (c0 > qi1     || sk0 != sqr1) ? -1.0e30f : sf[nf][2] * scale;
            sf[nf][3] = (c0 + 1 > qi1 || sk1 != sqr1) ? -1.0e30f : sf[nf][3] * scale;
        }

        // ---- online softmax ----
        float mx0 = -1.0e30f, mx1 = -1.0e30f;
#pragma unroll
        for (int nf = 0; nf < 8; nf++) {
            mx0 = fmaxf(mx0, fmaxf(sf[nf][0], sf[nf][1]));
            mx1 = fmaxf(mx1, fmaxf(sf[nf][2], sf[nf][3]));
        }
        mx0 = fmaxf(mx0, __shfl_xor_sync(0xffffffffu, mx0, 1));
        mx0 = fmaxf(mx0, __shfl_xor_sync(0xffffffffu, mx0, 2));
        mx1 = fmaxf(mx1, __shfl_xor_sync(0xffffffffu, mx1, 1));
        mx1 = fmaxf(mx1, __shfl_xor_sync(0xffffffffu, mx1, 2));
        float mn0 = fmaxf(m0, mx0), mn1 = fmaxf(m1, mx1);
        float a0 = __expf(m0 - mn0), a1 = __expf(m1 - mn1);
        float sum0 = 0.f, sum1 = 0.f;
        uint32_t ph[4][4], pl[4][4];
#pragma unroll
        for (int nf = 0; nf < 8; nf++) {
            float p0 = __expf(sf[nf][0] - mn0);
            float p1 = __expf(sf[nf][1] - mn0);
            float p2 = __expf(sf[nf][2] - mn1);
            float p3 = __expf(sf[nf][3] - mn1);
            sum0 += p0 + p1; sum1 += p2 + p3;
            __half2 h01 = __floats2half2_rn(p0, p1);
            float2 f01 = __half22float2(h01);
            __half2 e01 = __floats2half2_rn(p0 - f01.x, p1 - f01.y);
            __half2 h23 = __floats2half2_rn(p2, p3);
            float2 f23 = __half22float2(h23);
            __half2 e23 = __floats2half2_rn(p2 - f23.x, p3 - f23.y);
            int ksv = nf >> 1, up = (nf & 1) ? 2 : 0;
            ph[ksv][up + 0] = *(uint32_t*)&h01;
            ph[ksv][up + 1] = *(uint32_t*)&h23;
            pl[ksv][up + 0] = *(uint32_t*)&e01;
            pl[ksv][up + 1] = *(uint32_t*)&e23;
        }
        sum0 += __shfl_xor_sync(0xffffffffu, sum0, 1);
        sum0 += __shfl_xor_sync(0xffffffffu, sum0, 2);
        sum1 += __shfl_xor_sync(0xffffffffu, sum1, 1);
        sum1 += __shfl_xor_sync(0xffffffffu, sum1, 2);
        l0 = l0 * a0 + sum0; m0 = mn0;
        l1 = l1 * a1 + sum1; m1 = mn1;

        // ---- rescale O, then O += P V (fp16x3) ----
#pragma unroll
        for (int nf2 = 0; nf2 < 16; nf2++) {
            o[nf2][0] *= a0; o[nf2][1] *= a0;
            o[nf2][2] *= a1; o[nf2][3] *= a1;
        }
#pragma unroll
        for (int nf2 = 0; nf2 < 16; nf2++) {
            uint32_t vo = Vb + ((nf2 * 8 + v_row) * VROW + v_ch) * 2;
            uint32_t vh[8], vl[8];
            LDSM4(vh, vo);
            LDSM4(vh + 4, vo + 64);                       // +32 halves = ksv 2,3
            LDSM4(vl, vo + (HD * VROW) * 2);
            LDSM4(vl + 4, vo + (HD * VROW) * 2 + 64);
#pragma unroll
            for (int ksv = 0; ksv < 4; ksv++) {
                mma16816(o[nf2], ph[ksv], vh + ksv * 2);
                mma16816(o[nf2], pl[ksv], vh + ksv * 2);
                mma16816(o[nf2], ph[ksv], vl + ksv * 2);
            }
        }

        __syncthreads();
        if (kb + 2 <= kbe) F_ISSUE(kb + 2, st);
    }

    // ---- epilogue ----
    float i0 = 1.0f / l0, i1 = 1.0f / l1;
    int r0 = q0 + wid * 16 + lg;
#pragma unroll
    for (int nf2 = 0; nf2 < 16; nf2++) {
        int col = nf2 * 8 + lt * 2;
        size_t b0 = ((size_t)r0 * NH + h) * HD + col;
        size_t b1 = ((size_t)(r0 + 8) * NH + h) * HD + col;
        *(float2*)(Aout + b0) = make_float2(o[nf2][0] * i0, o[nf2][1] * i0);
        *(float2*)(Aout + b1) = make_float2(o[nf2][2] * i1, o[nf2][3] * i1);
    }
}

// ----------------------------------------------------------------
extern "C" void kernel_launch(void* const* d_in, const int* in_sizes, int n_in,
                              void* d_out, int out_size)
{
    const float* x   = (const float*)d_in[0];
    const float* wq  = (const float*)d_in[1];
    const float* wk  = (const float*)d_in[2];
    const float* wv  = (const float*)d_in[3];
    const float* wo  = (const float*)d_in[4];
    const float* fc  = (const float*)d_in[5];
    const float* fs  = (const float*)d_in[6];
    const int*   sid = (const int*)d_in[7];
    float* out = (float*)d_out;

    float *Qp, *Kp, *Vp, *Ap;
    __half *xh, *xl, *ah, *al, *wqkvh, *wqkvl, *woh, *wol;
    __half *qhp, *qlp, *khp, *klp, *vthp, *vtlp;
    cudaGetSymbolAddress((void**)&Qp, g_Q);
    cudaGetSymbolAddress((void**)&Kp, g_K);
    cudaGetSymbolAddress((void**)&Vp, g_V);
    cudaGetSymbolAddress((void**)&Ap, g_A);
    cudaGetSymbolAddress((void**)&xh, g_xh);
    cudaGetSymbolAddress((void**)&xl, g_xl);
    cudaGetSymbolAddress((void**)&ah, g_ah);
    cudaGetSymbolAddress((void**)&al, g_al);
    cudaGetSymbolAddress((void**)&wqkvh, g_wqkvh);
    cudaGetSymbolAddress((void**)&wqkvl, g_wqkvl);
    cudaGetSymbolAddress((void**)&woh, g_woh);
    cudaGetSymbolAddress((void**)&wol, g_wol);
    cudaGetSymbolAddress((void**)&qhp, g_qh);
    cudaGetSymbolAddress((void**)&qlp, g_ql);
    cudaGetSymbolAddress((void**)&khp, g_kh);
    cudaGetSymbolAddress((void**)&klp, g_kl);
    cudaGetSymbolAddress((void**)&vthp, g_vth);
    cudaGetSymbolAddress((void**)&vtlp, g_vtl);

    cudaFuncSetAttribute(gemm_hmma, cudaFuncAttributeMaxDynamicSharedMemorySize, GEMM_SMEM);
    cudaFuncSetAttribute(flash_hmma, cudaFuncAttributeMaxDynamicSharedMemorySize, FLASH_SMEM);

    pack_split<<<(T_TOK * DIM / 4 + 255) / 256, 256>>>(x, xh, xl, T_TOK * DIM / 4);
    pack_wT<<<dim3(DIM / 32, 2048 / 32), 256>>>(wq, wqkvh, wqkvl, 2048, 0);
    pack_wT<<<dim3(DIM / 32,  512 / 32), 256>>>(wk, wqkvh, wqkvl, 512, 2048);
    pack_wT<<<dim3(DIM / 32,  512 / 32), 256>>>(wv, wqkvh, wqkvl, 512, 2560);
    pack_wT<<<dim3(DIM / 32, 2048 / 32), 256>>>(wo, woh, wol, 2048, 0);

    // fused QKV projection
    gemm_hmma<<<dim3(3072 / BN, T_TOK / BM), 256, GEMM_SMEM>>>(
        xh, xl, wqkvh, wqkvl, Qp, Kp, Vp);

    rope_split<<<(T_TOK * (NH + NKV) * 64) / 256, 256>>>(Qp, Kp, fc, fs, qhp, qlp, khp, klp);
    transpose_v<<<dim3(T_TOK / 32, HD / 32, NKV), 256>>>(Vp, vthp, vtlp);

    flash_hmma<<<dim3(T_TOK / FQB, NH), 256, FLASH_SMEM>>>(
        qhp, qlp, khp, klp, vthp, vtlp, sid, Ap);

    pack_split<<<(T_TOK * DIM / 4 + 255) / 256, 256>>>(Ap, ah, al, T_TOK * DIM / 4);
    gemm_hmma<<<dim3(DIM / BN, T_TOK / BM), 256, GEMM_SMEM>>>(
        ah, al, woh, wol, out, nullptr, nullptr);
}

// round 10
// speedup vs baseline: 4.1305x; 1.3727x over previous
#include <cuda_runtime.h>
#include <cuda_fp16.h>
#include <cstdint>
#include <math.h>

// ---------------- problem constants ----------------
#define T_TOK   4096
#define DIM     2048
#define NH      16
#define NKV     4
#define HD      128

// ---------------- HMMA GEMM constants (BM=256, BN=128, 8 warps, 2-product) ----------------
#define BM 256
#define BN 128
#define BK 32
#define GPAD 40
#define GBH (256 * GPAD)              // 10240: Bh after Ah
#define GBL (GBH + 128 * GPAD)        // 15360: Bl
#define GSTG_H (GBL + 128 * GPAD)     // 20480 halves/stage
#define STAGE_B (GSTG_H * 2)          // 40960 B
#define NSTAGE 4
#define GEMM_SMEM (NSTAGE * STAGE_B)  // 163840 B

// ---------------- flash constants ----------------
#define FQB  128
#define FKB  64
#define KROW 136
#define VROW 72
#define QL_H   (FQB * KROW)
#define STG0_H (2 * FQB * KROW)
#define KL_H   (FKB * KROW)
#define VH_H   (2 * FKB * KROW)
#define STG_H  (VH_H + 2 * HD * VROW)
#define FLASH_SMEM ((STG0_H + 2 * STG_H) * 2)   // 212992 B

extern __shared__ __align__(16) char dyn_smem[];

// -------- scratch (device globals) --------
__device__ float g_Q[T_TOK * NH * HD];
__device__ float g_K[T_TOK * NKV * HD];
__device__ float g_V[T_TOK * NKV * HD];
__device__ float g_A[T_TOK * NH * HD];
__device__ __half g_xh[T_TOK * DIM],  g_xl[T_TOK * DIM];
__device__ __half g_ah[T_TOK * DIM],  g_al[T_TOK * DIM];
__device__ __half g_wqkvh[3072 * DIM], g_wqkvl[3072 * DIM];
__device__ __half g_woh[DIM * DIM],   g_wol[DIM * DIM];
__device__ __half g_qh[T_TOK * NH * HD],  g_ql[T_TOK * NH * HD];
__device__ __half g_kh[T_TOK * NKV * HD], g_kl[T_TOK * NKV * HD];
__device__ __half g_vth[NKV * HD * T_TOK], g_vtl[NKV * HD * T_TOK];

// ---------------- helpers ----------------
__device__ __forceinline__ uint32_t smem_u32(const void* p) {
    uint32_t a;
    asm("{ .reg .u64 t; cvta.to.shared.u64 t, %1; cvt.u32.u64 %0, t; }" : "=r"(a) : "l"(p));
    return a;
}
__device__ __forceinline__ void cp16(void* dst, const void* src) {
    uint32_t d;
    asm("{ .reg .u64 t; cvta.to.shared.u64 t, %1; cvt.u32.u64 %0, t; }" : "=r"(d) : "l"(dst));
    asm volatile("cp.async.cg.shared.global [%0], [%1], 16;" :: "r"(d), "l"(src));
}
__device__ __forceinline__ void mma16816(float* c, const uint32_t* a, const uint32_t* b) {
    asm volatile(
        "mma.sync.aligned.m16n8k16.row.col.f32.f16.f16.f32 "
        "{%0,%1,%2,%3}, {%4,%5,%6,%7}, {%8,%9}, {%0,%1,%2,%3};"
        : "+f"(c[0]), "+f"(c[1]), "+f"(c[2]), "+f"(c[3])
        : "r"(a[0]), "r"(a[1]), "r"(a[2]), "r"(a[3]), "r"(b[0]), "r"(b[1]));
}
#define LDSM4(R, a) \
    asm volatile("ldmatrix.sync.aligned.m8n8.x4.shared.b16 {%0,%1,%2,%3}, [%4];" \
        : "=r"((R)[0]), "=r"((R)[1]), "=r"((R)[2]), "=r"((R)[3]) : "r"(a))

// ---------------- pack: fp32 -> (hi, lo) fp16 ----------------
__global__ void __launch_bounds__(256) pack_split(const float* __restrict__ in,
                                                  __half* __restrict__ oh,
                                                  __half* __restrict__ ol, int n4) {
    int i = blockIdx.x * blockDim.x + threadIdx.x;
    if (i >= n4) return;
    float4 v = ((const float4*)in)[i];
    __half h0 = __float2half_rn(v.x), h1 = __float2half_rn(v.y);
    __half h2 = __float2half_rn(v.z), h3 = __float2half_rn(v.w);
    __half l0 = __float2half_rn(v.x - __half2float(h0));
    __half l1 = __float2half_rn(v.y - __half2float(h1));
    __half l2 = __float2half_rn(v.z - __half2float(h2));
    __half l3 = __float2half_rn(v.w - __half2float(h3));
    ((__half2*)oh)[i * 2 + 0] = __halves2half2(h0, h1);
    ((__half2*)oh)[i * 2 + 1] = __halves2half2(h2, h3);
    ((__half2*)ol)[i * 2 + 0] = __halves2half2(l0, l1);
    ((__half2*)ol)[i * 2 + 1] = __halves2half2(l2, l3);
}

// ---------------- pack: w[K][Nsrc] -> transposed [nbase+n][K] hi/lo ----------------
__global__ void __launch_bounds__(256) pack_wT(const float* __restrict__ w,
                                               __half* __restrict__ oh,
                                               __half* __restrict__ ol,
                                               int Nsrc, int nbase) {
    __shared__ float t[32][33];
    int k0 = blockIdx.x * 32, n0 = blockIdx.y * 32;
    int tid = threadIdx.x;
    int cc = tid & 31, rr = tid >> 5;
#pragma unroll
    for (int i = 0; i < 4; i++) {
        int row = rr + i * 8;
        t[row][cc] = w[(size_t)(k0 + row) * Nsrc + n0 + cc];
    }
    __syncthreads();
#pragma unroll
    for (int i = 0; i < 4; i++) {
        int n = rr + i * 8;
        float v = t[cc][n];
        __half h = __float2half_rn(v);
        __half l = __float2half_rn(v - __half2float(h));
        size_t o = (size_t)(nbase + n0 + n) * DIM + k0 + cc;
        oh[o] = h;
        ol[o] = l;
    }
}

// ---------------- HMMA GEMM: 256x128 tiles, 8 warps, 2-product (Ah*Bh + Ah*Bl) ----------------
__global__ void __launch_bounds__(256, 1) gemm_hmma(const __half* __restrict__ Ah,
                                                    const __half* __restrict__ Bh,
                                                    const __half* __restrict__ Bl,
                                                    float* __restrict__ Cq,
                                                    float* __restrict__ Ck,
                                                    float* __restrict__ Cv) {
    __half* sm = (__half*)dyn_smem;
    const int tid = threadIdx.x;
    const int wid = tid >> 5, lane = tid & 31;
    const int wm = (wid & 3) * 64, wn = (wid >> 2) * 64;
    const int lg = lane >> 2, lt = lane & 3;

    const size_t arow0 = (size_t)blockIdx.y * BM;
    const size_t brow0 = (size_t)blockIdx.x * BN;

    float acc[4][8][4];
#pragma unroll
    for (int mf = 0; mf < 4; mf++)
#pragma unroll
        for (int nf = 0; nf < 8; nf++)
#pragma unroll
            for (int q = 0; q < 4; q++) acc[mf][nf][q] = 0.f;

    const int NKT = DIM / BK;

#define G_ISSUE(KT, ST) do {                                                     \
    __half* _sb = sm + (ST) * GSTG_H;                                            \
    int _k0 = (KT) * BK;                                                         \
    _Pragma("unroll")                                                            \
    for (int _i = 0; _i < 8; _i++) {                                             \
        int _idx = tid + _i * 256;      /* 0..2047 */                            \
        if (_idx < 1024) {                                                       \
            int _row = _idx >> 2, _ch = _idx & 3;                                \
            cp16(_sb + _row * GPAD + _ch * 8,                                    \
                 Ah + (arow0 + _row) * DIM + _k0 + _ch * 8);                     \
        } else {                                                                 \
            int _j = _idx - 1024;                                                \
            int _sp = _j >> 9, _rem = _j & 511;                                  \
            int _row = _rem >> 2, _ch = _rem & 3;                                \
            const __half* _src = (_sp ? Bl : Bh)                                 \
                + (brow0 + _row) * DIM + _k0 + _ch * 8;                          \
            cp16(_sb + GBH + _sp * (128 * GPAD) + _row * GPAD + _ch * 8, _src);  \
        }                                                                        \
    }                                                                            \
    asm volatile("cp.async.commit_group;" ::: "memory");                         \
} while (0)

    G_ISSUE(0, 0);
    G_ISSUE(1, 1);
    G_ISSUE(2, 2);

    const uint32_t smb = smem_u32(sm);
    const int a_row = (lane & 15);
    const int a_ch  = (lane >> 4) * 8;
    const int b_row = ((lane >> 4) & 1) * 8 + (lane & 7);
    const int b_ch  = ((lane >> 3) & 1) * 8;

    for (int kt = 0; kt < NKT; kt++) {
        int st = kt % NSTAGE;
        if (kt + 1 < NKT) asm volatile("cp.async.wait_group 2;" ::: "memory");
        else              asm volatile("cp.async.wait_group 0;" ::: "memory");
        __syncthreads();
        if (kt + 3 < NKT) G_ISSUE(kt + 3, (kt + 3) % NSTAGE);

        const uint32_t sb = smb + st * STAGE_B;

#pragma unroll
        for (int ks = 0; ks < 2; ks++) {
            uint32_t ah[4][4];
#pragma unroll
            for (int mf = 0; mf < 4; mf++) {
                uint32_t ao = sb + ((wm + mf * 16 + a_row) * GPAD + ks * 16 + a_ch) * 2;
                LDSM4(ah[mf], ao);
            }
#pragma unroll
            for (int np = 0; np < 4; np++) {
                uint32_t bo = sb + (GBH + (wn + np * 16 + b_row) * GPAD + ks * 16 + b_ch) * 2;
                uint32_t b4h[4], b4l[4];
                LDSM4(b4h, bo);
                LDSM4(b4l, bo + (128 * GPAD) * 2);
#pragma unroll
                for (int half = 0; half < 2; half++) {
                    const uint32_t* bh2 = b4h + half * 2;
                    const uint32_t* bl2 = b4l + half * 2;
                    int nf = np * 2 + half;
#pragma unroll
                    for (int mf = 0; mf < 4; mf++) {
                        mma16816(acc[mf][nf], ah[mf], bh2);
                        mma16816(acc[mf][nf], ah[mf], bl2);
                    }
                }
            }
        }
    }

    float* Cb;
    int stride, colofs;
    int nblock = blockIdx.x * BN;
    if (Ck == nullptr || nblock < 2048) { Cb = Cq; stride = 2048; colofs = nblock; }
    else if (nblock < 2560)             { Cb = Ck; stride = 512;  colofs = nblock - 2048; }
    else                                { Cb = Cv; stride = 512;  colofs = nblock - 2560; }

#pragma unroll
    for (int mf = 0; mf < 4; mf++) {
        size_t row0 = arow0 + wm + mf * 16 + lg;
#pragma unroll
        for (int nf = 0; nf < 8; nf++) {
            int col = colofs + wn + nf * 8 + lt * 2;
            *(float2*)(Cb + row0 * stride + col) =
                make_float2(acc[mf][nf][0], acc[mf][nf][1]);
            *(float2*)(Cb + (row0 + 8) * stride + col) =
                make_float2(acc[mf][nf][2], acc[mf][nf][3]);
        }
    }
}

// ---------------- RoPE + hi/lo split of Q, K ----------------
__global__ void rope_split(const float* __restrict__ Q, const float* __restrict__ K,
                           const float* __restrict__ fcos, const float* __restrict__ fsin,
                           __half* __restrict__ qh, __half* __restrict__ ql,
                           __half* __restrict__ kh, __half* __restrict__ kl)
{
    int idx = blockIdx.x * blockDim.x + threadIdx.x;
    int pair = idx & 63;
    int rest = idx >> 6;
    int h = rest % (NH + NKV);
    int t = rest / (NH + NKV);
    float c = fcos[t * 64 + pair];
    float s = fsin[t * 64 + pair];
    const float* p;
    size_t off;
    __half *oh, *ol;
    if (h < NH) {
        off = ((size_t)t * NH + h) * HD + pair * 2;
        p = Q + off; oh = qh; ol = ql;
    } else {
        off = ((size_t)t * NKV + (h - NH)) * HD + pair * 2;
        p = K + off; oh = kh; ol = kl;
    }
    float x0 = p[0], x1 = p[1];
    float o0 = x0 * c - x1 * s;
    float o1 = x0 * s + x1 * c;
    __half h0 = __float2half_rn(o0);
    __half h1 = __float2half_rn(o1);
    oh[off]     = h0;
    oh[off + 1] = h1;
    ol[off]     = __float2half_rn(o0 - __half2float(h0));
    ol[off + 1] = __float2half_rn(o1 - __half2float(h1));
}

// ---------------- V transpose + split ----------------
__global__ void __launch_bounds__(256) transpose_v(const float* __restrict__ V,
                                                   __half* __restrict__ vth,
                                                   __half* __restrict__ vtl)
{
    __shared__ float t[32][33];
    int kv = blockIdx.z, t0 = blockIdx.x * 32, d0 = blockIdx.y * 32;
    int cc = threadIdx.x & 31, rr = threadIdx.x >> 5;
#pragma unroll
    for (int i = 0; i < 4; i++) {
        int tok = rr + i * 8;
        t[tok][cc] = V[((size_t)(t0 + tok) * NKV + kv) * HD + d0 + cc];
    }
    __syncthreads();
#pragma unroll
    for (int i = 0; i < 4; i++) {
        int dd = rr + i * 8;
        float v = t[cc][dd];
        __half h = __float2half_rn(v);
        size_t o = ((size_t)kv * HD + d0 + dd) * T_TOK + t0 + cc;
        vth[o] = h;
        vtl[o] = __float2half_rn(v - __half2float(h));
    }
}

// ---------------- flash attention on HMMA, ldmatrix ----------------
__global__ void __launch_bounds__(256) flash_hmma(
    const __half* __restrict__ qh, const __half* __restrict__ ql,
    const __half* __restrict__ kh, const __half* __restrict__ kl,
    const __half* __restrict__ vth, const __half* __restrict__ vtl,
    const int* __restrict__ sid, float* __restrict__ Aout)
{
    __half* S = (__half*)dyn_smem;
    const int tid = threadIdx.x, wid = tid >> 5, lane = tid & 31;
    const int lg = lane >> 2, lt = lane & 3;
    const int h = blockIdx.y, kv = h >> 2;
    const int q0 = (gridDim.x - 1 - blockIdx.x) * FQB;   // heavy blocks first

#pragma unroll
    for (int i = 0; i < 16; i++) {
        int id = tid + i * 256;
        int sp = id >> 11, rem = id & 2047;
        int row = rem >> 4, ch = rem & 15;
        const __half* src = (sp ? ql : qh) + ((size_t)(q0 + row) * NH + h) * HD + ch * 8;
        cp16(S + sp * QL_H + row * KROW + ch * 8, src);
    }
    asm volatile("cp.async.commit_group;" ::: "memory");

#define F_ISSUE(KB, ST) do {                                                          \
    __half* _s = S + STG0_H + (ST) * STG_H;                                           \
    int _t0 = (KB) * FKB;                                                             \
    _Pragma("unroll")                                                                 \
    for (int _i = 0; _i < 8; _i++) {                                                  \
        int _id = tid + _i * 256;                                                     \
        int _sp = _id >> 10, _rem = _id & 1023;                                       \
        int _row = _rem >> 4, _ch = _rem & 15;                                        \
        const __half* _src = (_sp ? kl : kh)                                          \
            + ((size_t)(_t0 + _row) * NKV + kv) * HD + _ch * 8;                       \
        cp16(_s + _sp * KL_H + _row * KROW + _ch * 8, _src);                          \
    }                                                                                 \
    _Pragma("unroll")                                                                 \
    for (int _i = 0; _i < 8; _i++) {                                                  \
        int _id = tid + _i * 256;                                                     \
        int _sp = _id >> 10, _rem = _id & 1023;                                       \
        int _row = _rem >> 3, _ch = _rem & 7;                                         \
        const __half* _src = (_sp ? vtl : vth)                                        \
            + ((size_t)kv * HD + _row) * T_TOK + _t0 + _ch * 8;                       \
        cp16(_s + VH_H + _sp * (HD * VROW) + _row * VROW + _ch * 8, _src);            \
    }                                                                                 \
    asm volatile("cp.async.commit_group;" ::: "memory");                              \
} while (0)

    const int qi0 = q0 + wid * 16 + lg, qi1 = qi0 + 8;
    const int sqr0 = sid[qi0], sqr1 = sid[qi1];
    const int sq_first = sid[q0];
    const int kbe = q0 / FKB + 1;
    int kb0 = kbe;
    for (int kb = 0; kb <= kbe; kb++) {
        if (sid[kb * FKB + FKB - 1] >= sq_first) { kb0 = kb; break; }
    }

    F_ISSUE(kb0, 0);
    if (kb0 + 1 <= kbe) F_ISSUE(kb0 + 1, 1);

    float o[16][4];
#pragma unroll
    for (int i = 0; i < 16; i++)
#pragma unroll
        for (int j = 0; j < 4; j++) o[i][j] = 0.f;
    float m0 = -1.0e30f, l0 = 0.f, m1 = -1.0e30f, l1 = 0.f;

    const float scale = 0.08838834764831845f;
    const uint32_t Sb = smem_u32(S);

    const uint32_t q_off = Sb + (((wid * 16 + (lane & 15)) * KROW) + (lane >> 4) * 8) * 2;
    const int k_row = ((lane >> 4) & 1) * 8 + (lane & 7);
    const int k_ch  = ((lane >> 3) & 1) * 8;
    const int v_row = lane & 7;
    const int v_ch  = (lane >> 3) * 8;

    for (int kb = kb0; kb <= kbe; kb++) {
        int st = (kb - kb0) & 1;
        if (kb + 1 <= kbe) asm volatile("cp.async.wait_group 1;" ::: "memory");
        else               asm volatile("cp.async.wait_group 0;" ::: "memory");
        __syncthreads();

        const uint32_t Kb = Sb + (STG0_H + st * STG_H) * 2;
        const uint32_t Vb = Kb + VH_H * 2;

        // ---- S = Q K^T (fp16x3) ----
        float sf[8][4];
#pragma unroll
        for (int nf = 0; nf < 8; nf++)
#pragma unroll
            for (int q = 0; q < 4; q++) sf[nf][q] = 0.f;

#pragma unroll
        for (int ks = 0; ks < 8; ks++) {
            uint32_t ah[4], al[4];
            LDSM4(ah, q_off + ks * 32);
            LDSM4(al, q_off + ks * 32 + QL_H * 2);
#pragma unroll
            for (int np = 0; np < 4; np++) {
                uint32_t bo = Kb + ((np * 16 + k_row) * KROW + ks * 16 + k_ch) * 2;
                uint32_t b4h[4], b4l[4];
                LDSM4(b4h, bo);
                LDSM4(b4l, bo + KL_H * 2);
#pragma unroll
                for (int half = 0; half < 2; half++) {
                    int nf = np * 2 + half;
                    mma16816(sf[nf], ah, b4h + half * 2);
                    mma16816(sf[nf], al, b4h + half * 2);
                    mma16816(sf[nf], ah, b4l + half * 2);
                }
            }
        }

        // ---- mask + scale ----
        const int kbase = kb * FKB;
#pragma unroll
        for (int nf = 0; nf < 8; nf++) {
            int c0 = kbase + nf * 8 + lt * 2;
            int sk0 = sid[c0], sk1 = sid[c0 + 1];
            sf[nf][0] = (c0 > qi0     || sk0 != sqr0) ? -1.0e30f : sf[nf][0] * scale;
            sf[nf][1] = (c0 + 1 > qi0 || sk1 != sqr0) ? -1.0e30f : sf[nf][1] * scale;
            sf[nf][2] = (c0 > qi1     || sk0 != sqr1) ? -1.0e30f : sf[nf][2] * scale;
            sf[nf][3] = (c0 + 1 > qi1 || sk1 != sqr1) ? -1.0e30f : sf[nf][3] * scale;
        }

        // ---- online softmax ----
        float mx0 = -1.0e30f, mx1 = -1.0e30f;
#pragma unroll
        for (int nf = 0; nf < 8; nf++) {
            mx0 = fmaxf(mx0, fmaxf(sf[nf][0], sf[nf][1]));
            mx1 = fmaxf(mx1, fmaxf(sf[nf][2], sf[nf][3]));
        }
        mx0 = fmaxf(mx0, __shfl_xor_sync(0xffffffffu, mx0, 1));
        mx0 = fmaxf(mx0, __shfl_xor_sync(0xffffffffu, mx0, 2));
        mx1 = fmaxf(mx1, __shfl_xor_sync(0xffffffffu, mx1, 1));
        mx1 = fmaxf(mx1, __shfl_xor_sync(0xffffffffu, mx1, 2));
        float mn0 = fmaxf(m0, mx0), mn1 = fmaxf(m1, mx1);
        float a0 = __expf(m0 - mn0), a1 = __expf(m1 - mn1);
        float sum0 = 0.f, sum1 = 0.f;
        uint32_t ph[4][4];
#pragma unroll
        for (int nf = 0; nf < 8; nf++) {
            float p0 = __expf(sf[nf][0] - mn0);
            float p1 = __expf(sf[nf][1] - mn0);
            float p2 = __expf(sf[nf][2] - mn1);
            float p3 = __expf(sf[nf][3] - mn1);
            sum0 += p0 + p1; sum1 += p2 + p3;
            __half2 h01 = __floats2half2_rn(p0, p1);
            __half2 h23 = __floats2half2_rn(p2, p3);
            int ksv = nf >> 1, up = (nf & 1) ? 2 : 0;
            ph[ksv][up + 0] = *(uint32_t*)&h01;
            ph[ksv][up + 1] = *(uint32_t*)&h23;
        }
        sum0 += __shfl_xor_sync(0xffffffffu, sum0, 1);
        sum0 += __shfl_xor_sync(0xffffffffu, sum0, 2);
        sum1 += __shfl_xor_sync(0xffffffffu, sum1, 1);
        sum1 += __shfl_xor_sync(0xffffffffu, sum1, 2);
        l0 = l0 * a0 + sum0; m0 = mn0;
        l1 = l1 * a1 + sum1; m1 = mn1;

        // ---- rescale O, then O += P (Vh + Vl)  (2-product) ----
#pragma unroll
        for (int nf2 = 0; nf2 < 16; nf2++) {
            o[nf2][0] *= a0; o[nf2][1] *= a0;
            o[nf2][2] *= a1; o[nf2][3] *= a1;
        }
#pragma unroll
        for (int nf2 = 0; nf2 < 16; nf2++) {
            uint32_t vo = Vb + ((nf2 * 8 + v_row) * VROW + v_ch) * 2;
            uint32_t vh[8], vl[8];
            LDSM4(vh, vo);
            LDSM4(vh + 4, vo + 64);
            LDSM4(vl, vo + (HD * VROW) * 2);
            LDSM4(vl + 4, vo + (HD * VROW) * 2 + 64);
#pragma unroll
            for (int ksv = 0; ksv < 4; ksv++) {
                mma16816(o[nf2], ph[ksv], vh + ksv * 2);
                mma16816(o[nf2], ph[ksv], vl + ksv * 2);
            }
        }

        __syncthreads();
        if (kb + 2 <= kbe) F_ISSUE(kb + 2, st);
    }

    // ---- epilogue ----
    float i0 = 1.0f / l0, i1 = 1.0f / l1;
    int r0 = q0 + wid * 16 + lg;
#pragma unroll
    for (int nf2 = 0; nf2 < 16; nf2++) {
        int col = nf2 * 8 + lt * 2;
        size_t b0 = ((size_t)r0 * NH + h) * HD + col;
        size_t b1 = ((size_t)(r0 + 8) * NH + h) * HD + col;
        *(float2*)(Aout + b0) = make_float2(o[nf2][0] * i0, o[nf2][1] * i0);
        *(float2*)(Aout + b1) = make_float2(o[nf2][2] * i1, o[nf2][3] * i1);
    }
}

// ----------------------------------------------------------------
extern "C" void kernel_launch(void* const* d_in, const int* in_sizes, int n_in,
                              void* d_out, int out_size)
{
    const float* x   = (const float*)d_in[0];
    const float* wq  = (const float*)d_in[1];
    const float* wk  = (const float*)d_in[2];
    const float* wv  = (const float*)d_in[3];
    const float* wo  = (const float*)d_in[4];
    const float* fc  = (const float*)d_in[5];
    const float* fs  = (const float*)d_in[6];
    const int*   sid = (const int*)d_in[7];
    float* out = (float*)d_out;

    float *Qp, *Kp, *Vp, *Ap;
    __half *xh, *xl, *ah, *al, *wqkvh, *wqkvl, *woh, *wol;
    __half *qhp, *qlp, *khp, *klp, *vthp, *vtlp;
    cudaGetSymbolAddress((void**)&Qp, g_Q);
    cudaGetSymbolAddress((void**)&Kp, g_K);
    cudaGetSymbolAddress((void**)&Vp, g_V);
    cudaGetSymbolAddress((void**)&Ap, g_A);
    cudaGetSymbolAddress((void**)&xh, g_xh);
    cudaGetSymbolAddress((void**)&xl, g_xl);
    cudaGetSymbolAddress((void**)&ah, g_ah);
    cudaGetSymbolAddress((void**)&al, g_al);
    cudaGetSymbolAddress((void**)&wqkvh, g_wqkvh);
    cudaGetSymbolAddress((void**)&wqkvl, g_wqkvl);
    cudaGetSymbolAddress((void**)&woh, g_woh);
    cudaGetSymbolAddress((void**)&wol, g_wol);
    cudaGetSymbolAddress((void**)&qhp, g_qh);
    cudaGetSymbolAddress((void**)&qlp, g_ql);
    cudaGetSymbolAddress((void**)&khp, g_kh);
    cudaGetSymbolAddress((void**)&klp, g_kl);
    cudaGetSymbolAddress((void**)&vthp, g_vth);
    cudaGetSymbolAddress((void**)&vtlp, g_vtl);

    cudaFuncSetAttribute(gemm_hmma, cudaFuncAttributeMaxDynamicSharedMemorySize, GEMM_SMEM);
    cudaFuncSetAttribute(flash_hmma, cudaFuncAttributeMaxDynamicSharedMemorySize, FLASH_SMEM);

    pack_split<<<(T_TOK * DIM / 4 + 255) / 256, 256>>>(x, xh, xl, T_TOK * DIM / 4);
    pack_wT<<<dim3(DIM / 32, 2048 / 32), 256>>>(wq, wqkvh, wqkvl, 2048, 0);
    pack_wT<<<dim3(DIM / 32,  512 / 32), 256>>>(wk, wqkvh, wqkvl, 512, 2048);
    pack_wT<<<dim3(DIM / 32,  512 / 32), 256>>>(wv, wqkvh, wqkvl, 512, 2560);
    pack_wT<<<dim3(DIM / 32, 2048 / 32), 256>>>(wo, woh, wol, 2048, 0);

    // fused QKV projection (A = xh only; B hi+lo)
    gemm_hmma<<<dim3(3072 / BN, T_TOK / BM), 256, GEMM_SMEM>>>(
        xh, wqkvh, wqkvl, Qp, Kp, Vp);

    rope_split<<<(T_TOK * (NH + NKV) * 64) / 256, 256>>>(Qp, Kp, fc, fs, qhp, qlp, khp, klp);
    transpose_v<<<dim3(T_TOK / 32, HD / 32, NKV), 256>>>(Vp, vthp, vtlp);

    flash_hmma<<<dim3(T_TOK / FQB, NH), 256, FLASH_SMEM>>>(
        qhp, qlp, khp, klp, vthp, vtlp, sid, Ap);

    pack_split<<<(T_TOK * DIM / 4 + 255) / 256, 256>>>(Ap, ah, al, T_TOK * DIM / 4);
    gemm_hmma<<<dim3(DIM / BN, T_TOK / BM), 256, GEMM_SMEM>>>(
        ah, woh, wol, out, nullptr, nullptr);
}

// round 11
// speedup vs baseline: 4.1977x; 1.0163x over previous
#include <cuda_runtime.h>
#include <cuda_fp16.h>
#include <cstdint>
#include <math.h>

// ---------------- problem constants ----------------
#define T_TOK   4096
#define DIM     2048
#define NH      16
#define NKV     4
#define HD      128

// ---------------- HMMA GEMM constants (BM=128, BN=128, 8 warps, 2 CTAs/SM) ----------------
#define BM 128
#define BN 128
#define BK 32
#define GPAD 40
#define GBH_OFF (128 * GPAD)            // 5120
#define GBL_OFF (GBH_OFF + 128 * GPAD)  // 10240
#define GSTG_H  (GBL_OFF + 128 * GPAD)  // 15360 halves/stage
#define STAGE_B (GSTG_H * 2)            // 30720 B
#define NSTAGE 3
#define GEMM_SMEM (NSTAGE * STAGE_B)    // 92160 B (x2 CTAs = 184 KB/SM)

// ---------------- flash constants ----------------
#define FQB  128
#define FKB  64
#define KROW 136
#define VROW 72
#define QL_H   (FQB * KROW)
#define STG0_H (2 * FQB * KROW)
#define KL_H   (FKB * KROW)
#define VH_H   (2 * FKB * KROW)
#define STG_H  (VH_H + 2 * HD * VROW)
#define FLASH_SMEM ((STG0_H + 2 * STG_H) * 2)   // 212992 B

extern __shared__ __align__(16) char dyn_smem[];

// -------- scratch (device globals) --------
__device__ float g_Q[T_TOK * NH * HD];
__device__ float g_K[T_TOK * NKV * HD];
__device__ float g_V[T_TOK * NKV * HD];
__device__ float g_A[T_TOK * NH * HD];
__device__ __half g_xh[T_TOK * DIM];
__device__ __half g_ah[T_TOK * DIM];
__device__ __half g_wqkvh[3072 * DIM], g_wqkvl[3072 * DIM];
__device__ __half g_woh[DIM * DIM],   g_wol[DIM * DIM];
__device__ __half g_qh[T_TOK * NH * HD],  g_ql[T_TOK * NH * HD];
__device__ __half g_kh[T_TOK * NKV * HD];
__device__ __half g_vth[NKV * HD * T_TOK], g_vtl[NKV * HD * T_TOK];

// ---------------- helpers ----------------
__device__ __forceinline__ uint32_t smem_u32(const void* p) {
    uint32_t a;
    asm("{ .reg .u64 t; cvta.to.shared.u64 t, %1; cvt.u32.u64 %0, t; }" : "=r"(a) : "l"(p));
    return a;
}
__device__ __forceinline__ void cp16(void* dst, const void* src) {
    uint32_t d;
    asm("{ .reg .u64 t; cvta.to.shared.u64 t, %1; cvt.u32.u64 %0, t; }" : "=r"(d) : "l"(dst));
    asm volatile("cp.async.cg.shared.global [%0], [%1], 16;" :: "r"(d), "l"(src));
}
__device__ __forceinline__ void mma16816(float* c, const uint32_t* a, const uint32_t* b) {
    asm volatile(
        "mma.sync.aligned.m16n8k16.row.col.f32.f16.f16.f32 "
        "{%0,%1,%2,%3}, {%4,%5,%6,%7}, {%8,%9}, {%0,%1,%2,%3};"
        : "+f"(c[0]), "+f"(c[1]), "+f"(c[2]), "+f"(c[3])
        : "r"(a[0]), "r"(a[1]), "r"(a[2]), "r"(a[3]), "r"(b[0]), "r"(b[1]));
}
#define LDSM4(R, a) \
    asm volatile("ldmatrix.sync.aligned.m8n8.x4.shared.b16 {%0,%1,%2,%3}, [%4];" \
        : "=r"((R)[0]), "=r"((R)[1]), "=r"((R)[2]), "=r"((R)[3]) : "r"(a))

// ---------------- pack x / A: fp32 -> hi fp16 only ----------------
__global__ void __launch_bounds__(256) pack_hi(const float* __restrict__ in,
                                               __half* __restrict__ oh, int n4) {
    int i = blockIdx.x * blockDim.x + threadIdx.x;
    if (i >= n4) return;
    float4 v = ((const float4*)in)[i];
    ((__half2*)oh)[i * 2 + 0] = __floats2half2_rn(v.x, v.y);
    ((__half2*)oh)[i * 2 + 1] = __floats2half2_rn(v.z, v.w);
}

// ---------------- fused weight transpose+split: wq/wk/wv/wo in one launch ----------------
__global__ void __launch_bounds__(256) pack_w_all(const float* __restrict__ wq,
                                                  const float* __restrict__ wk,
                                                  const float* __restrict__ wv,
                                                  const float* __restrict__ wo,
                                                  __half* __restrict__ qkvh,
                                                  __half* __restrict__ qkvl,
                                                  __half* __restrict__ woh,
                                                  __half* __restrict__ wol) {
    __shared__ float t[32][33];
    int k0 = blockIdx.x * 32;
    int by = blockIdx.y;
    const float* w; __half *oh, *ol;
    int Nsrc, nbase, n0;
    if (by < 64)       { w = wq; Nsrc = 2048; nbase = 0;    n0 = by * 32;        oh = qkvh; ol = qkvl; }
    else if (by < 80)  { w = wk; Nsrc = 512;  nbase = 2048; n0 = (by - 64) * 32; oh = qkvh; ol = qkvl; }
    else if (by < 96)  { w = wv; Nsrc = 512;  nbase = 2560; n0 = (by - 80) * 32; oh = qkvh; ol = qkvl; }
    else               { w = wo; Nsrc = 2048; nbase = 0;    n0 = (by - 96) * 32; oh = woh;  ol = wol;  }
    int tid = threadIdx.x;
    int cc = tid & 31, rr = tid >> 5;
#pragma unroll
    for (int i = 0; i < 4; i++) {
        int row = rr + i * 8;
        t[row][cc] = w[(size_t)(k0 + row) * Nsrc + n0 + cc];
    }
    __syncthreads();
#pragma unroll
    for (int i = 0; i < 4; i++) {
        int n = rr + i * 8;
        float v = t[cc][n];
        __half h = __float2half_rn(v);
        __half l = __float2half_rn(v - __half2float(h));
        size_t o = (size_t)(nbase + n0 + n) * DIM + k0 + cc;
        oh[o] = h;
        ol[o] = l;
    }
}

// ---------------- HMMA GEMM: 128x128 tiles, 8 warps, 2-product, 2 CTAs/SM ----------------
__global__ void __launch_bounds__(256, 2) gemm_hmma(const __half* __restrict__ Ah,
                                                    const __half* __restrict__ Bh,
                                                    const __half* __restrict__ Bl,
                                                    float* __restrict__ Cq,
                                                    float* __restrict__ Ck,
                                                    float* __restrict__ Cv) {
    __half* sm = (__half*)dyn_smem;
    const int tid = threadIdx.x;
    const int wid = tid >> 5, lane = tid & 31;
    const int wm = (wid & 1) * 64, wn = (wid >> 1) * 32;
    const int lg = lane >> 2, lt = lane & 3;

    const size_t arow0 = (size_t)blockIdx.y * BM;
    const size_t brow0 = (size_t)blockIdx.x * BN;

    float acc[4][4][4];
#pragma unroll
    for (int mf = 0; mf < 4; mf++)
#pragma unroll
        for (int nf = 0; nf < 4; nf++)
#pragma unroll
            for (int q = 0; q < 4; q++) acc[mf][nf][q] = 0.f;

    const int NKT = DIM / BK;

#define G_ISSUE(KT, ST) do {                                                     \
    __half* _sb = sm + (ST) * GSTG_H;                                            \
    int _k0 = (KT) * BK;                                                         \
    _Pragma("unroll")                                                            \
    for (int _i = 0; _i < 6; _i++) {                                             \
        int _idx = tid + _i * 256;      /* 0..1535 */                            \
        if (_idx < 512) {                                                        \
            int _row = _idx >> 2, _ch = _idx & 3;                                \
            cp16(_sb + _row * GPAD + _ch * 8,                                    \
                 Ah + (arow0 + _row) * DIM + _k0 + _ch * 8);                     \
        } else {                                                                 \
            int _j = _idx - 512;                                                 \
            int _sp = _j >> 9, _rem = _j & 511;                                  \
            int _row = _rem >> 2, _ch = _rem & 3;                                \
            const __half* _src = (_sp ? Bl : Bh)                                 \
                + (brow0 + _row) * DIM + _k0 + _ch * 8;                          \
            cp16(_sb + GBH_OFF + _sp * (128 * GPAD) + _row * GPAD + _ch * 8, _src); \
        }                                                                        \
    }                                                                            \
    asm volatile("cp.async.commit_group;" ::: "memory");                         \
} while (0)

    G_ISSUE(0, 0);
    G_ISSUE(1, 1);

    const uint32_t smb = smem_u32(sm);
    const int a_row = (lane & 15);
    const int a_ch  = (lane >> 4) * 8;
    const int b_row = ((lane >> 4) & 1) * 8 + (lane & 7);
    const int b_ch  = ((lane >> 3) & 1) * 8;

    for (int kt = 0; kt < NKT; kt++) {
        int st = kt % NSTAGE;
        if (kt + 1 < NKT) asm volatile("cp.async.wait_group 1;" ::: "memory");
        else              asm volatile("cp.async.wait_group 0;" ::: "memory");
        __syncthreads();
        if (kt + 2 < NKT) G_ISSUE(kt + 2, (kt + 2) % NSTAGE);

        const uint32_t sb = smb + st * STAGE_B;

#pragma unroll
        for (int ks = 0; ks < 2; ks++) {
            uint32_t ah[4][4];
#pragma unroll
            for (int mf = 0; mf < 4; mf++) {
                uint32_t ao = sb + ((wm + mf * 16 + a_row) * GPAD + ks * 16 + a_ch) * 2;
                LDSM4(ah[mf], ao);
            }
#pragma unroll
            for (int np = 0; np < 2; np++) {
                uint32_t bo = sb + (GBH_OFF + (wn + np * 16 + b_row) * GPAD + ks * 16 + b_ch) * 2;
                uint32_t b4h[4], b4l[4];
                LDSM4(b4h, bo);
                LDSM4(b4l, bo + (128 * GPAD) * 2);
#pragma unroll
                for (int half = 0; half < 2; half++) {
                    const uint32_t* bh2 = b4h + half * 2;
                    const uint32_t* bl2 = b4l + half * 2;
                    int nf = np * 2 + half;
#pragma unroll
                    for (int mf = 0; mf < 4; mf++) {
                        mma16816(acc[mf][nf], ah[mf], bh2);
                        mma16816(acc[mf][nf], ah[mf], bl2);
                    }
                }
            }
        }
    }

    float* Cb;
    int stride, colofs;
    int nblock = blockIdx.x * BN;
    if (Ck == nullptr || nblock < 2048) { Cb = Cq; stride = 2048; colofs = nblock; }
    else if (nblock < 2560)             { Cb = Ck; stride = 512;  colofs = nblock - 2048; }
    else                                { Cb = Cv; stride = 512;  colofs = nblock - 2560; }

#pragma unroll
    for (int mf = 0; mf < 4; mf++) {
        size_t row0 = arow0 + wm + mf * 16 + lg;
#pragma unroll
        for (int nf = 0; nf < 4; nf++) {
            int col = colofs + wn + nf * 8 + lt * 2;
            *(float2*)(Cb + row0 * stride + col) =
                make_float2(acc[mf][nf][0], acc[mf][nf][1]);
            *(float2*)(Cb + (row0 + 8) * stride + col) =
                make_float2(acc[mf][nf][2], acc[mf][nf][3]);
        }
    }
}

// ---------------- RoPE + split Q (hi/lo), K (hi only) ----------------
__global__ void rope_split(const float* __restrict__ Q, const float* __restrict__ K,
                           const float* __restrict__ fcos, const float* __restrict__ fsin,
                           __half* __restrict__ qh, __half* __restrict__ ql,
                           __half* __restrict__ kh)
{
    int idx = blockIdx.x * blockDim.x + threadIdx.x;
    int pair = idx & 63;
    int rest = idx >> 6;
    int h = rest % (NH + NKV);
    int t = rest / (NH + NKV);
    float c = fcos[t * 64 + pair];
    float s = fsin[t * 64 + pair];
    if (h < NH) {
        size_t off = ((size_t)t * NH + h) * HD + pair * 2;
        float x0 = Q[off], x1 = Q[off + 1];
        float o0 = x0 * c - x1 * s;
        float o1 = x0 * s + x1 * c;
        __half h0 = __float2half_rn(o0);
        __half h1 = __float2half_rn(o1);
        qh[off]     = h0;
        qh[off + 1] = h1;
        ql[off]     = __float2half_rn(o0 - __half2float(h0));
        ql[off + 1] = __float2half_rn(o1 - __half2float(h1));
    } else {
        size_t off = ((size_t)t * NKV + (h - NH)) * HD + pair * 2;
        float x0 = K[off], x1 = K[off + 1];
        float o0 = x0 * c - x1 * s;
        float o1 = x0 * s + x1 * c;
        kh[off]     = __float2half_rn(o0);
        kh[off + 1] = __float2half_rn(o1);
    }
}

// ---------------- V transpose + split ----------------
__global__ void __launch_bounds__(256) transpose_v(const float* __restrict__ V,
                                                   __half* __restrict__ vth,
                                                   __half* __restrict__ vtl)
{
    __shared__ float t[32][33];
    int kv = blockIdx.z, t0 = blockIdx.x * 32, d0 = blockIdx.y * 32;
    int cc = threadIdx.x & 31, rr = threadIdx.x >> 5;
#pragma unroll
    for (int i = 0; i < 4; i++) {
        int tok = rr + i * 8;
        t[tok][cc] = V[((size_t)(t0 + tok) * NKV + kv) * HD + d0 + cc];
    }
    __syncthreads();
#pragma unroll
    for (int i = 0; i < 4; i++) {
        int dd = rr + i * 8;
        float v = t[cc][dd];
        __half h = __float2half_rn(v);
        size_t o = ((size_t)kv * HD + d0 + dd) * T_TOK + t0 + cc;
        vth[o] = h;
        vtl[o] = __float2half_rn(v - __half2float(h));
    }
}

// ---------------- flash attention: QK = (Qh+Ql)*Kh, PV = P*(Vh+Vl) ----------------
__global__ void __launch_bounds__(256) flash_hmma(
    const __half* __restrict__ qh, const __half* __restrict__ ql,
    const __half* __restrict__ kh,
    const __half* __restrict__ vth, const __half* __restrict__ vtl,
    const int* __restrict__ sid, float* __restrict__ Aout)
{
    __half* S = (__half*)dyn_smem;
    const int tid = threadIdx.x, wid = tid >> 5, lane = tid & 31;
    const int lg = lane >> 2, lt = lane & 3;
    const int h = blockIdx.y, kv = h >> 2;
    const int q0 = (gridDim.x - 1 - blockIdx.x) * FQB;   // heavy blocks first

#pragma unroll
    for (int i = 0; i < 16; i++) {
        int id = tid + i * 256;
        int sp = id >> 11, rem = id & 2047;
        int row = rem >> 4, ch = rem & 15;
        const __half* src = (sp ? ql : qh) + ((size_t)(q0 + row) * NH + h) * HD + ch * 8;
        cp16(S + sp * QL_H + row * KROW + ch * 8, src);
    }
    asm volatile("cp.async.commit_group;" ::: "memory");

#define F_ISSUE(KB, ST) do {                                                          \
    __half* _s = S + STG0_H + (ST) * STG_H;                                           \
    int _t0 = (KB) * FKB;                                                             \
    _Pragma("unroll")                                                                 \
    for (int _i = 0; _i < 4; _i++) {      /* K hi only: 64 rows x 16 ch */            \
        int _id = tid + _i * 256;                                                     \
        int _row = _id >> 4, _ch = _id & 15;                                          \
        cp16(_s + _row * KROW + _ch * 8,                                              \
             kh + ((size_t)(_t0 + _row) * NKV + kv) * HD + _ch * 8);                  \
    }                                                                                 \
    _Pragma("unroll")                                                                 \
    for (int _i = 0; _i < 8; _i++) {      /* Vt: 2 splits x 128 rows x 8 ch */        \
        int _id = tid + _i * 256;                                                     \
        int _sp = _id >> 10, _rem = _id & 1023;                                       \
        int _row = _rem >> 3, _ch = _rem & 7;                                         \
        const __half* _src = (_sp ? vtl : vth)                                        \
            + ((size_t)kv * HD + _row) * T_TOK + _t0 + _ch * 8;                       \
        cp16(_s + VH_H + _sp * (HD * VROW) + _row * VROW + _ch * 8, _src);            \
    }                                                                                 \
    asm volatile("cp.async.commit_group;" ::: "memory");                              \
} while (0)

    const int qi0 = q0 + wid * 16 + lg, qi1 = qi0 + 8;
    const int sqr0 = sid[qi0], sqr1 = sid[qi1];
    const int sq_first = sid[q0];
    const int kbe = q0 / FKB + 1;
    int kb0 = kbe;
    for (int kb = 0; kb <= kbe; kb++) {
        if (sid[kb * FKB + FKB - 1] >= sq_first) { kb0 = kb; break; }
    }

    F_ISSUE(kb0, 0);
    if (kb0 + 1 <= kbe) F_ISSUE(kb0 + 1, 1);

    float o[16][4];
#pragma unroll
    for (int i = 0; i < 16; i++)
#pragma unroll
        for (int j = 0; j < 4; j++) o[i][j] = 0.f;
    float m0 = -1.0e30f, l0 = 0.f, m1 = -1.0e30f, l1 = 0.f;

    const float scale = 0.08838834764831845f;
    const uint32_t Sb = smem_u32(S);

    const uint32_t q_off = Sb + (((wid * 16 + (lane & 15)) * KROW) + (lane >> 4) * 8) * 2;
    const int k_row = ((lane >> 4) & 1) * 8 + (lane & 7);
    const int k_ch  = ((lane >> 3) & 1) * 8;
    const int v_row = lane & 7;
    const int v_ch  = (lane >> 3) * 8;

    for (int kb = kb0; kb <= kbe; kb++) {
        int st = (kb - kb0) & 1;
        if (kb + 1 <= kbe) asm volatile("cp.async.wait_group 1;" ::: "memory");
        else               asm volatile("cp.async.wait_group 0;" ::: "memory");
        __syncthreads();

        const uint32_t Kb = Sb + (STG0_H + st * STG_H) * 2;
        const uint32_t Vb = Kb + VH_H * 2;

        // ---- S = (Qh + Ql) Kh^T ----
        float sf[8][4];
#pragma unroll
        for (int nf = 0; nf < 8; nf++)
#pragma unroll
            for (int q = 0; q < 4; q++) sf[nf][q] = 0.f;

#pragma unroll
        for (int ks = 0; ks < 8; ks++) {
            uint32_t ah[4], al[4];
            LDSM4(ah, q_off + ks * 32);
            LDSM4(al, q_off + ks * 32 + QL_H * 2);
#pragma unroll
            for (int np = 0; np < 4; np++) {
                uint32_t bo = Kb + ((np * 16 + k_row) * KROW + ks * 16 + k_ch) * 2;
                uint32_t b4h[4];
                LDSM4(b4h, bo);
#pragma unroll
                for (int half = 0; half < 2; half++) {
                    int nf = np * 2 + half;
                    mma16816(sf[nf], ah, b4h + half * 2);
                    mma16816(sf[nf], al, b4h + half * 2);
                }
            }
        }

        // ---- mask + scale ----
        const int kbase = kb * FKB;
#pragma unroll
        for (int nf = 0; nf < 8; nf++) {
            int c0 = kbase + nf * 8 + lt * 2;
            int sk0 = sid[c0], sk1 = sid[c0 + 1];
            sf[nf][0] = (c0 > qi0     || sk0 != sqr0) ? -1.0e30f : sf[nf][0] * scale;
            sf[nf][1] = (c0 + 1 > qi0 || sk1 != sqr0) ? -1.0e30f : sf[nf][1] * scale;
            sf[nf][2] = (c0 > qi1     || sk0 != sqr1) ? -1.0e30f : sf[nf][2] * scale;
            sf[nf][3] = (c0 + 1 > qi1 || sk1 != sqr1) ? -1.0e30f : sf[nf][3] * scale;
        }

        // ---- online softmax ----
        float mx0 = -1.0e30f, mx1 = -1.0e30f;
#pragma unroll
        for (int nf = 0; nf < 8; nf++) {
            mx0 = fmaxf(mx0, fmaxf(sf[nf][0], sf[nf][1]));
            mx1 = fmaxf(mx1, fmaxf(sf[nf][2], sf[nf][3]));
        }
        mx0 = fmaxf(mx0, __shfl_xor_sync(0xffffffffu, mx0, 1));
        mx0 = fmaxf(mx0, __shfl_xor_sync(0xffffffffu, mx0, 2));
        mx1 = fmaxf(mx1, __shfl_xor_sync(0xffffffffu, mx1, 1));
        mx1 = fmaxf(mx1, __shfl_xor_sync(0xffffffffu, mx1, 2));
        float mn0 = fmaxf(m0, mx0), mn1 = fmaxf(m1, mx1);
        float a0 = __expf(m0 - mn0), a1 = __expf(m1 - mn1);
        float sum0 = 0.f, sum1 = 0.f;
        uint32_t ph[4][4];
#pragma unroll
        for (int nf = 0; nf < 8; nf++) {
            float p0 = __expf(sf[nf][0] - mn0);
            float p1 = __expf(sf[nf][1] - mn0);
            float p2 = __expf(sf[nf][2] - mn1);
            float p3 = __expf(sf[nf][3] - mn1);
            sum0 += p0 + p1; sum1 += p2 + p3;
            __half2 h01 = __floats2half2_rn(p0, p1);
            __half2 h23 = __floats2half2_rn(p2, p3);
            int ksv = nf >> 1, up = (nf & 1) ? 2 : 0;
            ph[ksv][up + 0] = *(uint32_t*)&h01;
            ph[ksv][up + 1] = *(uint32_t*)&h23;
        }
        sum0 += __shfl_xor_sync(0xffffffffu, sum0, 1);
        sum0 += __shfl_xor_sync(0xffffffffu, sum0, 2);
        sum1 += __shfl_xor_sync(0xffffffffu, sum1, 1);
        sum1 += __shfl_xor_sync(0xffffffffu, sum1, 2);
        l0 = l0 * a0 + sum0; m0 = mn0;
        l1 = l1 * a1 + sum1; m1 = mn1;

        // ---- rescale O, then O += P (Vh + Vl) ----
#pragma unroll
        for (int nf2 = 0; nf2 < 16; nf2++) {
            o[nf2][0] *= a0; o[nf2][1] *= a0;
            o[nf2][2] *= a1; o[nf2][3] *= a1;
        }
#pragma unroll
        for (int nf2 = 0; nf2 < 16; nf2++) {
            uint32_t vo = Vb + ((nf2 * 8 + v_row) * VROW + v_ch) * 2;
            uint32_t vh[8], vl[8];
            LDSM4(vh, vo);
            LDSM4(vh + 4, vo + 64);
            LDSM4(vl, vo + (HD * VROW) * 2);
            LDSM4(vl + 4, vo + (HD * VROW) * 2 + 64);
#pragma unroll
            for (int ksv = 0; ksv < 4; ksv++) {
                mma16816(o[nf2], ph[ksv], vh + ksv * 2);
                mma16816(o[nf2], ph[ksv], vl + ksv * 2);
            }
        }

        __syncthreads();
        if (kb + 2 <= kbe) F_ISSUE(kb + 2, st);
    }

    // ---- epilogue ----
    float i0 = 1.0f / l0, i1 = 1.0f / l1;
    int r0 = q0 + wid * 16 + lg;
#pragma unroll
    for (int nf2 = 0; nf2 < 16; nf2++) {
        int col = nf2 * 8 + lt * 2;
        size_t b0 = ((size_t)r0 * NH + h) * HD + col;
        size_t b1 = ((size_t)(r0 + 8) * NH + h) * HD + col;
        *(float2*)(Aout + b0) = make_float2(o[nf2][0] * i0, o[nf2][1] * i0);
        *(float2*)(Aout + b1) = make_float2(o[nf2][2] * i1, o[nf2][3] * i1);
    }
}

// ----------------------------------------------------------------
extern "C" void kernel_launch(void* const* d_in, const int* in_sizes, int n_in,
                              void* d_out, int out_size)
{
    const float* x   = (const float*)d_in[0];
    const float* wq  = (const float*)d_in[1];
    const float* wk  = (const float*)d_in[2];
    const float* wv  = (const float*)d_in[3];
    const float* wo  = (const float*)d_in[4];
    const float* fc  = (const float*)d_in[5];
    const float* fs  = (const float*)d_in[6];
    const int*   sid = (const int*)d_in[7];
    float* out = (float*)d_out;

    float *Qp, *Kp, *Vp, *Ap;
    __half *xh, *ah, *wqkvh, *wqkvl, *woh, *wol;
    __half *qhp, *qlp, *khp, *vthp, *vtlp;
    cudaGetSymbolAddress((void**)&Qp, g_Q);
    cudaGetSymbolAddress((void**)&Kp, g_K);
    cudaGetSymbolAddress((void**)&Vp, g_V);
    cudaGetSymbolAddress((void**)&Ap, g_A);
    cudaGetSymbolAddress((void**)&xh, g_xh);
    cudaGetSymbolAddress((void**)&ah, g_ah);
    cudaGetSymbolAddress((void**)&wqkvh, g_wqkvh);
    cudaGetSymbolAddress((void**)&wqkvl, g_wqkvl);
    cudaGetSymbolAddress((void**)&woh, g_woh);
    cudaGetSymbolAddress((void**)&wol, g_wol);
    cudaGetSymbolAddress((void**)&qhp, g_qh);
    cudaGetSymbolAddress((void**)&qlp, g_ql);
    cudaGetSymbolAddress((void**)&khp, g_kh);
    cudaGetSymbolAddress((void**)&vthp, g_vth);
    cudaGetSymbolAddress((void**)&vtlp, g_vtl);

    cudaFuncSetAttribute(gemm_hmma, cudaFuncAttributeMaxDynamicSharedMemorySize, GEMM_SMEM);
    cudaFuncSetAttribute(flash_hmma, cudaFuncAttributeMaxDynamicSharedMemorySize, FLASH_SMEM);

    // 1: x -> fp16 hi
    pack_hi<<<(T_TOK * DIM / 4 + 255) / 256, 256>>>(x, xh, T_TOK * DIM / 4);
    // 2: all weights transpose+split (fused)
    pack_w_all<<<dim3(DIM / 32, 160), 256>>>(wq, wk, wv, wo, wqkvh, wqkvl, woh, wol);
    // 3: fused QKV projection
    gemm_hmma<<<dim3(3072 / BN, T_TOK / BM), 256, GEMM_SMEM>>>(
        xh, wqkvh, wqkvl, Qp, Kp, Vp);
    // 4: RoPE
    rope_split<<<(T_TOK * (NH + NKV) * 64) / 256, 256>>>(Qp, Kp, fc, fs, qhp, qlp, khp);
    // 5: V transpose
    transpose_v<<<dim3(T_TOK / 32, HD / 32, NKV), 256>>>(Vp, vthp, vtlp);
    // 6: flash attention  (ncu -s 5 -c 1 should land here)
    flash_hmma<<<dim3(T_TOK / FQB, NH), 256, FLASH_SMEM>>>(
        qhp, qlp, khp, vthp, vtlp, sid, Ap);
    // 7: A -> fp16 hi
    pack_hi<<<(T_TOK * DIM / 4 + 255) / 256, 256>>>(Ap, ah, T_TOK * DIM / 4);
    // 8: output projection
    gemm_hmma<<<dim3(DIM / BN, T_TOK / BM), 256, GEMM_SMEM>>>(
        ah, woh, wol, out, nullptr, nullptr);
}

// round 12
// speedup vs baseline: 5.3041x; 1.2636x over previous
#include <cuda_runtime.h>
#include <cuda_fp16.h>
#include <cstdint>
#include <math.h>

// ---------------- problem constants ----------------
#define T_TOK   4096
#define DIM     2048
#define NH      16
#define NKV     4
#define HD      128

// ---------------- HMMA GEMM constants ----------------
#define BM 128
#define BN 128
#define BK 32
#define GPAD 40
#define GBH_OFF (128 * GPAD)
#define GBL_OFF (GBH_OFF + 128 * GPAD)
#define GSTG_H  (GBL_OFF + 128 * GPAD)  // 15360 halves/stage
#define STAGE_B (GSTG_H * 2)            // 30720 B
#define NSTAGE 3
#define GEMM_SMEM (NSTAGE * STAGE_B)    // 92160 B

// ---------------- flash constants ----------------
#define FQB  128
#define FKB  64
#define KROW 136
#define VROW 72
#define QL_H   (FQB * KROW)
#define STG0_H (2 * FQB * KROW)         // 34816 (Q hi+lo)
#define VH_H   (FKB * KROW)             // 8704 (K hi tile)
#define STG_H  (VH_H + HD * VROW)       // 17920 halves (K hi + V hi)
#define FLASH_SMEM ((STG0_H + 2 * STG_H) * 2)   // 141312 B

extern __shared__ __align__(16) char dyn_smem[];

// -------- scratch (device globals) --------
__device__ float  g_V[T_TOK * NKV * HD];
__device__ __half g_xh[T_TOK * DIM];
__device__ __half g_ah[T_TOK * DIM];
__device__ __half g_wqkvh[3072 * DIM], g_wqkvl[3072 * DIM];
__device__ __half g_woh[DIM * DIM],   g_wol[DIM * DIM];   // wol kept (unused in MMA) for layout symmetry
__device__ __half g_qh[T_TOK * NH * HD],  g_ql[T_TOK * NH * HD];
__device__ __half g_kh[T_TOK * NKV * HD];
__device__ __half g_vth[NKV * HD * T_TOK];

// ---------------- helpers ----------------
__device__ __forceinline__ uint32_t smem_u32(const void* p) {
    uint32_t a;
    asm("{ .reg .u64 t; cvta.to.shared.u64 t, %1; cvt.u32.u64 %0, t; }" : "=r"(a) : "l"(p));
    return a;
}
__device__ __forceinline__ void cp16(void* dst, const void* src) {
    uint32_t d;
    asm("{ .reg .u64 t; cvta.to.shared.u64 t, %1; cvt.u32.u64 %0, t; }" : "=r"(d) : "l"(dst));
    asm volatile("cp.async.cg.shared.global [%0], [%1], 16;" :: "r"(d), "l"(src));
}
__device__ __forceinline__ void mma16816(float* c, const uint32_t* a, const uint32_t* b) {
    asm volatile(
        "mma.sync.aligned.m16n8k16.row.col.f32.f16.f16.f32 "
        "{%0,%1,%2,%3}, {%4,%5,%6,%7}, {%8,%9}, {%0,%1,%2,%3};"
        : "+f"(c[0]), "+f"(c[1]), "+f"(c[2]), "+f"(c[3])
        : "r"(a[0]), "r"(a[1]), "r"(a[2]), "r"(a[3]), "r"(b[0]), "r"(b[1]));
}
#define LDSM4(R, a) \
    asm volatile("ldmatrix.sync.aligned.m8n8.x4.shared.b16 {%0,%1,%2,%3}, [%4];" \
        : "=r"((R)[0]), "=r"((R)[1]), "=r"((R)[2]), "=r"((R)[3]) : "r"(a))

// ---------------- pack x: fp32 -> hi fp16 ----------------
__global__ void __launch_bounds__(256) pack_hi(const float* __restrict__ in,
                                               __half* __restrict__ oh, int n4) {
    int i = blockIdx.x * blockDim.x + threadIdx.x;
    if (i >= n4) return;
    float4 v = ((const float4*)in)[i];
    ((__half2*)oh)[i * 2 + 0] = __floats2half2_rn(v.x, v.y);
    ((__half2*)oh)[i * 2 + 1] = __floats2half2_rn(v.z, v.w);
}

// ---------------- fused weight transpose+split ----------------
__global__ void __launch_bounds__(256) pack_w_all(const float* __restrict__ wq,
                                                  const float* __restrict__ wk,
                                                  const float* __restrict__ wv,
                                                  const float* __restrict__ wo,
                                                  __half* __restrict__ qkvh,
                                                  __half* __restrict__ qkvl,
                                                  __half* __restrict__ woh) {
    __shared__ float t[32][33];
    int k0 = blockIdx.x * 32;
    int by = blockIdx.y;
    const float* w; __half *oh, *ol;
    int Nsrc, nbase, n0;
    if (by < 64)       { w = wq; Nsrc = 2048; nbase = 0;    n0 = by * 32;        oh = qkvh; ol = qkvl; }
    else if (by < 80)  { w = wk; Nsrc = 512;  nbase = 2048; n0 = (by - 64) * 32; oh = qkvh; ol = qkvl; }
    else if (by < 96)  { w = wv; Nsrc = 512;  nbase = 2560; n0 = (by - 80) * 32; oh = qkvh; ol = qkvl; }
    else               { w = wo; Nsrc = 2048; nbase = 0;    n0 = (by - 96) * 32; oh = woh;  ol = nullptr; }
    int tid = threadIdx.x;
    int cc = tid & 31, rr = tid >> 5;
#pragma unroll
    for (int i = 0; i < 4; i++) {
        int row = rr + i * 8;
        t[row][cc] = w[(size_t)(k0 + row) * Nsrc + n0 + cc];
    }
    __syncthreads();
#pragma unroll
    for (int i = 0; i < 4; i++) {
        int n = rr + i * 8;
        float v = t[cc][n];
        __half h = __float2half_rn(v);
        size_t o = (size_t)(nbase + n0 + n) * DIM + k0 + cc;
        oh[o] = h;
        if (ol) ol[o] = __float2half_rn(v - __half2float(h));
    }
}

// ---------------- HMMA GEMM, templated epilogue ----------------
// MODE 0: QKV — 2-product (Bh+Bl), epilogue applies RoPE, writes qh/ql/kh fp16 + V fp32
// MODE 1: WO  — 1-product (Bh only), plain fp32 output
template<int MODE>
__global__ void __launch_bounds__(256, 2) gemm_hmma(const __half* __restrict__ Ah,
                                                    const __half* __restrict__ Bh,
                                                    const __half* __restrict__ Bl,
                                                    __half* __restrict__ qh,
                                                    __half* __restrict__ ql,
                                                    __half* __restrict__ kh,
                                                    float* __restrict__ Vout,
                                                    const float* __restrict__ fc,
                                                    const float* __restrict__ fs) {
    __half* sm = (__half*)dyn_smem;
    const int tid = threadIdx.x;
    const int wid = tid >> 5, lane = tid & 31;
    const int wm = (wid & 1) * 64, wn = (wid >> 1) * 32;
    const int lg = lane >> 2, lt = lane & 3;

    const size_t arow0 = (size_t)blockIdx.y * BM;
    const size_t brow0 = (size_t)blockIdx.x * BN;
    constexpr int NCOPY = (MODE == 0) ? 6 : 4;

    float acc[4][4][4];
#pragma unroll
    for (int mf = 0; mf < 4; mf++)
#pragma unroll
        for (int nf = 0; nf < 4; nf++)
#pragma unroll
            for (int q = 0; q < 4; q++) acc[mf][nf][q] = 0.f;

    const int NKT = DIM / BK;

#define G_ISSUE(KT, ST) do {                                                     \
    __half* _sb = sm + (ST) * GSTG_H;                                            \
    int _k0 = (KT) * BK;                                                         \
    _Pragma("unroll")                                                            \
    for (int _i = 0; _i < NCOPY; _i++) {                                         \
        int _idx = tid + _i * 256;                                               \
        if (_idx < 512) {                                                        \
            int _row = _idx >> 2, _ch = _idx & 3;                                \
            cp16(_sb + _row * GPAD + _ch * 8,                                    \
                 Ah + (arow0 + _row) * DIM + _k0 + _ch * 8);                     \
        } else {                                                                 \
            int _j = _idx - 512;                                                 \
            int _sp = _j >> 9, _rem = _j & 511;                                  \
            int _row = _rem >> 2, _ch = _rem & 3;                                \
            const __half* _src = (_sp ? Bl : Bh)                                 \
                + (brow0 + _row) * DIM + _k0 + _ch * 8;                          \
            cp16(_sb + GBH_OFF + _sp * (128 * GPAD) + _row * GPAD + _ch * 8, _src); \
        }                                                                        \
    }                                                                            \
    asm volatile("cp.async.commit_group;" ::: "memory");                         \
} while (0)

    G_ISSUE(0, 0);
    G_ISSUE(1, 1);

    const uint32_t smb = smem_u32(sm);
    const int a_row = (lane & 15);
    const int a_ch  = (lane >> 4) * 8;
    const int b_row = ((lane >> 4) & 1) * 8 + (lane & 7);
    const int b_ch  = ((lane >> 3) & 1) * 8;

    for (int kt = 0; kt < NKT; kt++) {
        int st = kt % NSTAGE;
        if (kt + 1 < NKT) asm volatile("cp.async.wait_group 1;" ::: "memory");
        else              asm volatile("cp.async.wait_group 0;" ::: "memory");
        __syncthreads();
        if (kt + 2 < NKT) G_ISSUE(kt + 2, (kt + 2) % NSTAGE);

        const uint32_t sb = smb + st * STAGE_B;

#pragma unroll
        for (int ks = 0; ks < 2; ks++) {
            uint32_t ah[4][4];
#pragma unroll
            for (int mf = 0; mf < 4; mf++) {
                uint32_t ao = sb + ((wm + mf * 16 + a_row) * GPAD + ks * 16 + a_ch) * 2;
                LDSM4(ah[mf], ao);
            }
#pragma unroll
            for (int np = 0; np < 2; np++) {
                uint32_t bo = sb + (GBH_OFF + (wn + np * 16 + b_row) * GPAD + ks * 16 + b_ch) * 2;
                uint32_t b4h[4];
                LDSM4(b4h, bo);
                uint32_t b4l[4];
                if (MODE == 0) LDSM4(b4l, bo + (128 * GPAD) * 2);
#pragma unroll
                for (int half = 0; half < 2; half++) {
                    int nf = np * 2 + half;
#pragma unroll
                    for (int mf = 0; mf < 4; mf++) {
                        mma16816(acc[mf][nf], ah[mf], b4h + half * 2);
                        if (MODE == 0) mma16816(acc[mf][nf], ah[mf], b4l + half * 2);
                    }
                }
            }
        }
    }

    // ---- epilogue ----
    const int nblock = blockIdx.x * BN;
#pragma unroll
    for (int mf = 0; mf < 4; mf++) {
        size_t row0 = arow0 + wm + mf * 16 + lg;
        size_t row1 = row0 + 8;
#pragma unroll
        for (int nf = 0; nf < 4; nf++) {
            int ncol = nblock + wn + nf * 8 + lt * 2;
            if (MODE == 1) {
                // plain fp32 output (wo GEMM): Vout = out, stride 2048
                *(float2*)(Vout + row0 * 2048 + ncol) = make_float2(acc[mf][nf][0], acc[mf][nf][1]);
                *(float2*)(Vout + row1 * 2048 + ncol) = make_float2(acc[mf][nf][2], acc[mf][nf][3]);
            } else if (ncol < 2048) {
                // Q with RoPE -> qh/ql fp16
                int pair = (ncol & 127) >> 1;
                float c0 = fc[row0 * 64 + pair], s0 = fs[row0 * 64 + pair];
                float c1 = fc[row1 * 64 + pair], s1 = fs[row1 * 64 + pair];
                float q00 = acc[mf][nf][0] * c0 - acc[mf][nf][1] * s0;
                float q01 = acc[mf][nf][0] * s0 + acc[mf][nf][1] * c0;
                float q10 = acc[mf][nf][2] * c1 - acc[mf][nf][3] * s1;
                float q11 = acc[mf][nf][2] * s1 + acc[mf][nf][3] * c1;
                __half2 h0 = __floats2half2_rn(q00, q01);
                __half2 h1 = __floats2half2_rn(q10, q11);
                float2 f0 = __half22float2(h0), f1 = __half22float2(h1);
                *(__half2*)(qh + row0 * 2048 + ncol) = h0;
                *(__half2*)(qh + row1 * 2048 + ncol) = h1;
                *(__half2*)(ql + row0 * 2048 + ncol) = __floats2half2_rn(q00 - f0.x, q01 - f0.y);
                *(__half2*)(ql + row1 * 2048 + ncol) = __floats2half2_rn(q10 - f1.x, q11 - f1.y);
            } else if (ncol < 2560) {
                // K with RoPE -> kh fp16 (hi only)
                int kcol = ncol - 2048;
                int pair = (kcol & 127) >> 1;
                float c0 = fc[row0 * 64 + pair], s0 = fs[row0 * 64 + pair];
                float c1 = fc[row1 * 64 + pair], s1 = fs[row1 * 64 + pair];
                float k00 = acc[mf][nf][0] * c0 - acc[mf][nf][1] * s0;
                float k01 = acc[mf][nf][0] * s0 + acc[mf][nf][1] * c0;
                float k10 = acc[mf][nf][2] * c1 - acc[mf][nf][3] * s1;
                float k11 = acc[mf][nf][2] * s1 + acc[mf][nf][3] * c1;
                *(__half2*)(kh + row0 * 512 + kcol) = __floats2half2_rn(k00, k01);
                *(__half2*)(kh + row1 * 512 + kcol) = __floats2half2_rn(k10, k11);
            } else {
                // V plain fp32 (for later transpose)
                int vcol = ncol - 2560;
                *(float2*)(Vout + row0 * 512 + vcol) = make_float2(acc[mf][nf][0], acc[mf][nf][1]);
                *(float2*)(Vout + row1 * 512 + vcol) = make_float2(acc[mf][nf][2], acc[mf][nf][3]);
            }
        }
    }
}

// ---------------- V transpose (hi only) ----------------
__global__ void __launch_bounds__(256) transpose_v(const float* __restrict__ V,
                                                   __half* __restrict__ vth)
{
    __shared__ float t[32][33];
    int kv = blockIdx.z, t0 = blockIdx.x * 32, d0 = blockIdx.y * 32;
    int cc = threadIdx.x & 31, rr = threadIdx.x >> 5;
#pragma unroll
    for (int i = 0; i < 4; i++) {
        int tok = rr + i * 8;
        t[tok][cc] = V[((size_t)(t0 + tok) * NKV + kv) * HD + d0 + cc];
    }
    __syncthreads();
#pragma unroll
    for (int i = 0; i < 4; i++) {
        int dd = rr + i * 8;
        size_t o = ((size_t)kv * HD + d0 + dd) * T_TOK + t0 + cc;
        vth[o] = __float2half_rn(t[cc][dd]);
    }
}

// ---------------- flash attention: QK = (Qh+Ql)*Kh, PV = P*Vh, fp16 out ----------------
__global__ void __launch_bounds__(256) flash_hmma(
    const __half* __restrict__ qh, const __half* __restrict__ ql,
    const __half* __restrict__ kh, const __half* __restrict__ vth,
    const int* __restrict__ sid, __half* __restrict__ Aout)
{
    __half* S = (__half*)dyn_smem;
    const int tid = threadIdx.x, wid = tid >> 5, lane = tid & 31;
    const int lg = lane >> 2, lt = lane & 3;
    const int h = blockIdx.y, kv = h >> 2;
    const int q0 = (gridDim.x - 1 - blockIdx.x) * FQB;

#pragma unroll
    for (int i = 0; i < 16; i++) {
        int id = tid + i * 256;
        int sp = id >> 11, rem = id & 2047;
        int row = rem >> 4, ch = rem & 15;
        const __half* src = (sp ? ql : qh) + ((size_t)(q0 + row) * NH + h) * HD + ch * 8;
        cp16(S + sp * QL_H + row * KROW + ch * 8, src);
    }
    asm volatile("cp.async.commit_group;" ::: "memory");

#define F_ISSUE(KB, ST) do {                                                          \
    __half* _s = S + STG0_H + (ST) * STG_H;                                           \
    int _t0 = (KB) * FKB;                                                             \
    _Pragma("unroll")                                                                 \
    for (int _i = 0; _i < 4; _i++) {      /* K hi: 64 rows x 16 ch */                 \
        int _id = tid + _i * 256;                                                     \
        int _row = _id >> 4, _ch = _id & 15;                                          \
        cp16(_s + _row * KROW + _ch * 8,                                              \
             kh + ((size_t)(_t0 + _row) * NKV + kv) * HD + _ch * 8);                  \
    }                                                                                 \
    _Pragma("unroll")                                                                 \
    for (int _i = 0; _i < 4; _i++) {      /* V hi: 128 rows x 8 ch */                 \
        int _id = tid + _i * 256;                                                     \
        int _row = _id >> 3, _ch = _id & 7;                                           \
        cp16(_s + VH_H + _row * VROW + _ch * 8,                                       \
             vth + ((size_t)kv * HD + _row) * T_TOK + _t0 + _ch * 8);                 \
    }                                                                                 \
    asm volatile("cp.async.commit_group;" ::: "memory");                              \
} while (0)

    const int qi0 = q0 + wid * 16 + lg, qi1 = qi0 + 8;
    const int sqr0 = sid[qi0], sqr1 = sid[qi1];
    const int sq_first = sid[q0];
    const int kbe = q0 / FKB + 1;
    int kb0 = kbe;
    for (int kb = 0; kb <= kbe; kb++) {
        if (sid[kb * FKB + FKB - 1] >= sq_first) { kb0 = kb; break; }
    }

    F_ISSUE(kb0, 0);
    if (kb0 + 1 <= kbe) F_ISSUE(kb0 + 1, 1);

    float o[16][4];
#pragma unroll
    for (int i = 0; i < 16; i++)
#pragma unroll
        for (int j = 0; j < 4; j++) o[i][j] = 0.f;
    float m0 = -1.0e30f, l0 = 0.f, m1 = -1.0e30f, l1 = 0.f;

    const float scale = 0.08838834764831845f;
    const uint32_t Sb = smem_u32(S);

    const uint32_t q_off = Sb + (((wid * 16 + (lane & 15)) * KROW) + (lane >> 4) * 8) * 2;
    const int k_row = ((lane >> 4) & 1) * 8 + (lane & 7);
    const int k_ch  = ((lane >> 3) & 1) * 8;
    const int v_row = lane & 7;
    const int v_ch  = (lane >> 3) * 8;

    for (int kb = kb0; kb <= kbe; kb++) {
        int st = (kb - kb0) & 1;
        if (kb + 1 <= kbe) asm volatile("cp.async.wait_group 1;" ::: "memory");
        else               asm volatile("cp.async.wait_group 0;" ::: "memory");
        __syncthreads();

        const uint32_t Kb = Sb + (STG0_H + st * STG_H) * 2;
        const uint32_t Vb = Kb + VH_H * 2;

        // ---- S = (Qh + Ql) Kh^T ----
        float sf[8][4];
#pragma unroll
        for (int nf = 0; nf < 8; nf++)
#pragma unroll
            for (int q = 0; q < 4; q++) sf[nf][q] = 0.f;

#pragma unroll
        for (int ks = 0; ks < 8; ks++) {
            uint32_t ah[4], al[4];
            LDSM4(ah, q_off + ks * 32);
            LDSM4(al, q_off + ks * 32 + QL_H * 2);
#pragma unroll
            for (int np = 0; np < 4; np++) {
                uint32_t bo = Kb + ((np * 16 + k_row) * KROW + ks * 16 + k_ch) * 2;
                uint32_t b4h[4];
                LDSM4(b4h, bo);
#pragma unroll
                for (int half = 0; half < 2; half++) {
                    int nf = np * 2 + half;
                    mma16816(sf[nf], ah, b4h + half * 2);
                    mma16816(sf[nf], al, b4h + half * 2);
                }
            }
        }

        // ---- mask + scale ----
        const int kbase = kb * FKB;
#pragma unroll
        for (int nf = 0; nf < 8; nf++) {
            int c0 = kbase + nf * 8 + lt * 2;
            int sk0 = sid[c0], sk1 = sid[c0 + 1];
            sf[nf][0] = (c0 > qi0     || sk0 != sqr0) ? -1.0e30f : sf[nf][0] * scale;
            sf[nf][1] = (c0 + 1 > qi0 || sk1 != sqr0) ? -1.0e30f : sf[nf][1] * scale;
            sf[nf][2] = (c0 > qi1     || sk0 != sqr1) ? -1.0e30f : sf[nf][2] * scale;
            sf[nf][3] = (c0 + 1 > qi1 || sk1 != sqr1) ? -1.0e30f : sf[nf][3] * scale;
        }

        // ---- online softmax ----
        float mx0 = -1.0e30f, mx1 = -1.0e30f;
#pragma unroll
        for (int nf = 0; nf < 8; nf++) {
            mx0 = fmaxf(mx0, fmaxf(sf[nf][0], sf[nf][1]));
            mx1 = fmaxf(mx1, fmaxf(sf[nf][2], sf[nf][3]));
        }
        mx0 = fmaxf(mx0, __shfl_xor_sync(0xffffffffu, mx0, 1));
        mx0 = fmaxf(mx0, __shfl_xor_sync(0xffffffffu, mx0, 2));
        mx1 = fmaxf(mx1, __shfl_xor_sync(0xffffffffu, mx1, 1));
        mx1 = fmaxf(mx1, __shfl_xor_sync(0xffffffffu, mx1, 2));
        float mn0 = fmaxf(m0, mx0), mn1 = fmaxf(m1, mx1);
        float a0 = __expf(m0 - mn0), a1 = __expf(m1 - mn1);
        float sum0 = 0.f, sum1 = 0.f;
        uint32_t ph[4][4];
#pragma unroll
        for (int nf = 0; nf < 8; nf++) {
            float p0 = __expf(sf[nf][0] - mn0);
            float p1 = __expf(sf[nf][1] - mn0);
            float p2 = __expf(sf[nf][2] - mn1);
            float p3 = __expf(sf[nf][3] - mn1);
            sum0 += p0 + p1; sum1 += p2 + p3;
            __half2 h01 = __floats2half2_rn(p0, p1);
            __half2 h23 = __floats2half2_rn(p2, p3);
            int ksv = nf >> 1, up = (nf & 1) ? 2 : 0;
            ph[ksv][up + 0] = *(uint32_t*)&h01;
            ph[ksv][up + 1] = *(uint32_t*)&h23;
        }
        sum0 += __shfl_xor_sync(0xffffffffu, sum0, 1);
        sum0 += __shfl_xor_sync(0xffffffffu, sum0, 2);
        sum1 += __shfl_xor_sync(0xffffffffu, sum1, 1);
        sum1 += __shfl_xor_sync(0xffffffffu, sum1, 2);
        l0 = l0 * a0 + sum0; m0 = mn0;
        l1 = l1 * a1 + sum1; m1 = mn1;

        // ---- rescale O, then O += P Vh ----
#pragma unroll
        for (int nf2 = 0; nf2 < 16; nf2++) {
            o[nf2][0] *= a0; o[nf2][1] *= a0;
            o[nf2][2] *= a1; o[nf2][3] *= a1;
        }
#pragma unroll
        for (int nf2 = 0; nf2 < 16; nf2++) {
            uint32_t vo = Vb + ((nf2 * 8 + v_row) * VROW + v_ch) * 2;
            uint32_t vh[8];
            LDSM4(vh, vo);
            LDSM4(vh + 4, vo + 64);
#pragma unroll
            for (int ksv = 0; ksv < 4; ksv++)
                mma16816(o[nf2], ph[ksv], vh + ksv * 2);
        }

        __syncthreads();
        if (kb + 2 <= kbe) F_ISSUE(kb + 2, st);
    }

    // ---- epilogue: fp16 output ----
    float i0 = 1.0f / l0, i1 = 1.0f / l1;
    int r0 = q0 + wid * 16 + lg;
#pragma unroll
    for (int nf2 = 0; nf2 < 16; nf2++) {
        int col = nf2 * 8 + lt * 2;
        size_t b0 = ((size_t)r0 * NH + h) * HD + col;
        size_t b1 = ((size_t)(r0 + 8) * NH + h) * HD + col;
        *(__half2*)(Aout + b0) = __floats2half2_rn(o[nf2][0] * i0, o[nf2][1] * i0);
        *(__half2*)(Aout + b1) = __floats2half2_rn(o[nf2][2] * i1, o[nf2][3] * i1);
    }
}

// ----------------------------------------------------------------
extern "C" void kernel_launch(void* const* d_in, const int* in_sizes, int n_in,
                              void* d_out, int out_size)
{
    const float* x   = (const float*)d_in[0];
    const float* wq  = (const float*)d_in[1];
    const float* wk  = (const float*)d_in[2];
    const float* wv  = (const float*)d_in[3];
    const float* wo  = (const float*)d_in[4];
    const float* fc  = (const float*)d_in[5];
    const float* fs  = (const float*)d_in[6];
    const int*   sid = (const int*)d_in[7];
    float* out = (float*)d_out;

    float *Vp;
    __half *xh, *ah, *wqkvh, *wqkvl, *woh;
    __half *qhp, *qlp, *khp, *vthp;
    cudaGetSymbolAddress((void**)&Vp, g_V);
    cudaGetSymbolAddress((void**)&xh, g_xh);
    cudaGetSymbolAddress((void**)&ah, g_ah);
    cudaGetSymbolAddress((void**)&wqkvh, g_wqkvh);
    cudaGetSymbolAddress((void**)&wqkvl, g_wqkvl);
    cudaGetSymbolAddress((void**)&woh, g_woh);
    cudaGetSymbolAddress((void**)&qhp, g_qh);
    cudaGetSymbolAddress((void**)&qlp, g_ql);
    cudaGetSymbolAddress((void**)&khp, g_kh);
    cudaGetSymbolAddress((void**)&vthp, g_vth);

    cudaFuncSetAttribute(gemm_hmma<0>, cudaFuncAttributeMaxDynamicSharedMemorySize, GEMM_SMEM);
    cudaFuncSetAttribute(gemm_hmma<1>, cudaFuncAttributeMaxDynamicSharedMemorySize, GEMM_SMEM);
    cudaFuncSetAttribute(flash_hmma, cudaFuncAttributeMaxDynamicSharedMemorySize, FLASH_SMEM);

    // 1: x -> fp16 hi
    pack_hi<<<(T_TOK * DIM / 4 + 255) / 256, 256>>>(x, xh, T_TOK * DIM / 4);
    // 2: weights transpose+split (fused)
    pack_w_all<<<dim3(DIM / 32, 160), 256>>>(wq, wk, wv, wo, wqkvh, wqkvl, woh);
    // 3: fused QKV projection with RoPE epilogue -> qh/ql/kh fp16, V fp32
    gemm_hmma<0><<<dim3(3072 / BN, T_TOK / BM), 256, GEMM_SMEM>>>(
        xh, wqkvh, wqkvl, qhp, qlp, khp, Vp, fc, fs);
    // 4: V transpose -> vth
    transpose_v<<<dim3(T_TOK / 32, HD / 32, NKV), 256>>>(Vp, vthp);
    // 5: flash attention -> ah fp16
    flash_hmma<<<dim3(T_TOK / FQB, NH), 256, FLASH_SMEM>>>(
        qhp, qlp, khp, vthp, sid, ah);
    // 6: output projection (1-product) -> out fp32
    gemm_hmma<1><<<dim3(DIM / BN, T_TOK / BM), 256, GEMM_SMEM>>>(
        ah, woh, nullptr, nullptr, nullptr, nullptr, out, nullptr, nullptr);
}